// round 2
// baseline (speedup 1.0000x reference)
#include <cuda_runtime.h>
#include <math.h>

#define MIN_VAL (-99999999.0f)

// Shapes: query [1024,4,256] f32, node [512,128,256] f32,
//         maskq [4,1024] i32, maskn [128,512] i32.
// Outputs concatenated in d_out: out_ss [512,128,256], out_sq [1024,128,256], cs [512,128,256].
// num_node = 32, scale = 1/sqrt(256) = 0.0625.

// Scratch (256 MB each) — static device arrays per allocation rules.
static __device__ float g_prod[67108864]; // [128][512][1024] scores (later wts1 in place)
static __device__ float g_w2[67108864];   // [128][512][1024] col-softmax weights (wts2 transposed-store)

// ---------------------------------------------------------------------------
// K1: prod[b,s,t] = valid ? 0.0625 * dot(node[s,b,:], query[t,b>>5,:]) : MIN_VAL
// NT GEMM, 128x128x8 tiles, 8x8 microtile, 256 threads.
// ---------------------------------------------------------------------------
__global__ __launch_bounds__(256) void k_prod(const float* __restrict__ query,
                                              const float* __restrict__ node,
                                              const int* __restrict__ maskq,
                                              const int* __restrict__ maskn) {
    __shared__ float As[8][128];
    __shared__ float Bs[8][128];
    const int b  = blockIdx.z;
    const int b1 = b >> 5;
    const int m0 = blockIdx.y * 128;  // S2 tile (512 -> 4)
    const int n0 = blockIdx.x * 128;  // S1 tile (1024 -> 8)
    const int tid = threadIdx.x;
    const int tx = tid & 15, ty = tid >> 4;
    const int lr = tid >> 1;
    const int lc = (tid & 1) << 2;

    // A element (m,k) = node[((m0+m)*128 + b)*256 + k]
    const float* gA = node + (size_t)b * 256 + (size_t)(m0 + lr) * 32768 + lc;
    // B element (n,k) = query[((n0+n)*4 + b1)*256 + k]
    const float* gB = query + (size_t)b1 * 256 + (size_t)(n0 + lr) * 1024 + lc;

    float acc[8][8];
#pragma unroll
    for (int i = 0; i < 8; i++)
#pragma unroll
        for (int j = 0; j < 8; j++) acc[i][j] = 0.f;

    for (int k0 = 0; k0 < 256; k0 += 8) {
        float4 av = *(const float4*)(gA + k0);
        float4 bv = *(const float4*)(gB + k0);
        __syncthreads();
        As[lc + 0][lr] = av.x; As[lc + 1][lr] = av.y;
        As[lc + 2][lr] = av.z; As[lc + 3][lr] = av.w;
        Bs[lc + 0][lr] = bv.x; Bs[lc + 1][lr] = bv.y;
        Bs[lc + 2][lr] = bv.z; Bs[lc + 3][lr] = bv.w;
        __syncthreads();
#pragma unroll
        for (int k = 0; k < 8; k++) {
            float4 a0 = *(const float4*)&As[k][ty * 8];
            float4 a1 = *(const float4*)&As[k][ty * 8 + 4];
            float4 b0 = *(const float4*)&Bs[k][tx * 8];
            float4 b1v = *(const float4*)&Bs[k][tx * 8 + 4];
            float a[8]  = {a0.x, a0.y, a0.z, a0.w, a1.x, a1.y, a1.z, a1.w};
            float bb[8] = {b0.x, b0.y, b0.z, b0.w, b1v.x, b1v.y, b1v.z, b1v.w};
#pragma unroll
            for (int i = 0; i < 8; i++)
#pragma unroll
                for (int j = 0; j < 8; j++) acc[i][j] = fmaf(a[i], bb[j], acc[i][j]);
        }
    }

    int nm[8], qm[8];
#pragma unroll
    for (int i = 0; i < 8; i++) nm[i] = maskn[b * 512 + m0 + ty * 8 + i];
#pragma unroll
    for (int j = 0; j < 8; j++) qm[j] = maskq[b1 * 1024 + n0 + tx * 8 + j];

    float* C = g_prod + ((size_t)b * 512 + m0 + ty * 8) * 1024 + n0 + tx * 8;
#pragma unroll
    for (int i = 0; i < 8; i++) {
        const int mr = nm[i];
        float4 o0, o1;
        o0.x = (mr | qm[0]) ? MIN_VAL : acc[i][0] * 0.0625f;
        o0.y = (mr | qm[1]) ? MIN_VAL : acc[i][1] * 0.0625f;
        o0.z = (mr | qm[2]) ? MIN_VAL : acc[i][2] * 0.0625f;
        o0.w = (mr | qm[3]) ? MIN_VAL : acc[i][3] * 0.0625f;
        o1.x = (mr | qm[4]) ? MIN_VAL : acc[i][4] * 0.0625f;
        o1.y = (mr | qm[5]) ? MIN_VAL : acc[i][5] * 0.0625f;
        o1.z = (mr | qm[6]) ? MIN_VAL : acc[i][6] * 0.0625f;
        o1.w = (mr | qm[7]) ? MIN_VAL : acc[i][7] * 0.0625f;
        *(float4*)(C + (size_t)i * 1024)     = o0;
        *(float4*)(C + (size_t)i * 1024 + 4) = o1;
    }
}

// ---------------------------------------------------------------------------
// K3: column softmax over s: g_w2[b,s,t] = exp(prod[b,s,t]) / sum_s exp(prod[b,s,t])
// (stored in [b,s,t] layout = wts2[b,t,s]). Masked entries (-1e8) underflow to 0;
// all-dead columns -> 0 via L==0 guard. Block = (32 t-cols, 8 s-lanes).
// Pass 1 stores exp() into g_w2 (avoids recomputing expf); pass 2 scales in place.
// ---------------------------------------------------------------------------
__global__ __launch_bounds__(256) void k_colsoftmax() {
    const int b = blockIdx.y;
    const int t = blockIdx.x * 32 + threadIdx.x;
    const int ty = threadIdx.y;
    const float* P = g_prod + (size_t)b * 524288 + t;
    float* W = g_w2 + (size_t)b * 524288 + t;
    float l = 0.f;
    for (int s = ty; s < 512; s += 8) {
        float e = expf(P[(size_t)s * 1024]);
        W[(size_t)s * 1024] = e;
        l += e;
    }
    __shared__ float sl[8][32];
    sl[ty][threadIdx.x] = l;
    __syncthreads();
    float L = 0.f;
#pragma unroll
    for (int r = 0; r < 8; r++) L += sl[r][threadIdx.x];
    const float inv = (L > 0.f) ? 1.f / L : 0.f;
    for (int s = ty; s < 512; s += 8)
        W[(size_t)s * 1024] *= inv;
}

// ---------------------------------------------------------------------------
// K2: row softmax over t, in place on g_prod -> wts1. One block per row.
// ---------------------------------------------------------------------------
__global__ __launch_bounds__(256) void k_rowsoftmax() {
    const size_t row = blockIdx.x;
    float* P = g_prod + row * 1024;
    const int tid = threadIdx.x;
    float4 v = *((const float4*)P + tid);
    float e0 = expf(v.x), e1 = expf(v.y), e2 = expf(v.z), e3 = expf(v.w);
    float s = e0 + e1 + e2 + e3;
#pragma unroll
    for (int o = 16; o; o >>= 1) s += __shfl_xor_sync(0xffffffffu, s, o);
    __shared__ float ssum[8];
    const int wid = tid >> 5, lid = tid & 31;
    if (lid == 0) ssum[wid] = s;
    __syncthreads();
    float S = 0.f;
#pragma unroll
    for (int i = 0; i < 8; i++) S += ssum[i];
    const float inv = (S > 0.f) ? 1.f / S : 0.f;
    v.x = e0 * inv; v.y = e1 * inv; v.z = e2 * inv; v.w = e3 * inv;
    *((float4*)P + tid) = v;
}

// ---------------------------------------------------------------------------
// K4: out_sq[t,b,d] = sum_s g_w2[b,s,t] * node[s,b,d]   (TN GEMM per b)
// ---------------------------------------------------------------------------
__global__ __launch_bounds__(256) void k_outsq(const float* __restrict__ node,
                                               float* __restrict__ out_sq) {
    __shared__ float As[8][128];
    __shared__ float Bs[8][128];
    const int b  = blockIdx.z;
    const int m0 = blockIdx.y * 128;  // S1 (1024 -> 8)
    const int n0 = blockIdx.x * 128;  // D (256 -> 2)
    const int tid = threadIdx.x;
    const int tx = tid & 15, ty = tid >> 4;
    const int r  = tid >> 5;          // k lane
    const int c4 = (tid & 31) << 2;   // col

    const float* gA = g_w2 + (size_t)b * 524288 + m0 + c4;  // (k,m): + k*1024
    const float* gB = node + (size_t)b * 256 + n0 + c4;     // (k,n): + k*32768

    float acc[8][8];
#pragma unroll
    for (int i = 0; i < 8; i++)
#pragma unroll
        for (int j = 0; j < 8; j++) acc[i][j] = 0.f;

    for (int k0 = 0; k0 < 512; k0 += 8) {
        float4 av = *(const float4*)(gA + (size_t)(k0 + r) * 1024);
        float4 bv = *(const float4*)(gB + (size_t)(k0 + r) * 32768);
        __syncthreads();
        *(float4*)&As[r][c4] = av;
        *(float4*)&Bs[r][c4] = bv;
        __syncthreads();
#pragma unroll
        for (int k = 0; k < 8; k++) {
            float4 a0 = *(const float4*)&As[k][ty * 8];
            float4 a1 = *(const float4*)&As[k][ty * 8 + 4];
            float4 b0 = *(const float4*)&Bs[k][tx * 8];
            float4 b1v = *(const float4*)&Bs[k][tx * 8 + 4];
            float a[8]  = {a0.x, a0.y, a0.z, a0.w, a1.x, a1.y, a1.z, a1.w};
            float bb[8] = {b0.x, b0.y, b0.z, b0.w, b1v.x, b1v.y, b1v.z, b1v.w};
#pragma unroll
            for (int i = 0; i < 8; i++)
#pragma unroll
                for (int j = 0; j < 8; j++) acc[i][j] = fmaf(a[i], bb[j], acc[i][j]);
        }
    }
    float* C = out_sq + (size_t)(m0 + ty * 8) * 32768 + (size_t)b * 256 + n0 + tx * 8;
#pragma unroll
    for (int i = 0; i < 8; i++) {
        float4 o0 = {acc[i][0], acc[i][1], acc[i][2], acc[i][3]};
        float4 o1 = {acc[i][4], acc[i][5], acc[i][6], acc[i][7]};
        *(float4*)(C + (size_t)i * 32768)     = o0;
        *(float4*)(C + (size_t)i * 32768 + 4) = o1;
    }
}

// ---------------------------------------------------------------------------
// K5/K6: C[s,b,d] = sum_t wts1[b,s,t] * B[t, (b>>bshift), d]  (NN GEMM per b)
// K5: B=query (ldB=1024, bshift=5) -> out_ss; K6: B=out_sq (ldB=32768, bshift=0) -> cs.
// ---------------------------------------------------------------------------
__global__ __launch_bounds__(256) void k_nn(const float* __restrict__ Bg, int ldB, int bshift,
                                            float* __restrict__ Cg) {
    __shared__ float As[8][128];
    __shared__ float Bs[8][128];
    const int b  = blockIdx.z;
    const int m0 = blockIdx.y * 128;  // S2 (512 -> 4)
    const int n0 = blockIdx.x * 128;  // D (256 -> 2)
    const int tid = threadIdx.x;
    const int tx = tid & 15, ty = tid >> 4;
    const int lr = tid >> 1;
    const int lc = (tid & 1) << 2;
    const int r  = tid >> 5;
    const int c4 = (tid & 31) << 2;

    // A element (m,k) = g_prod[(b*512 + m)*1024 + k]  (wts1, in place)
    const float* gA = g_prod + ((size_t)b * 512 + m0 + lr) * 1024 + lc;
    // B element (k,n) = Bg[(b>>bshift)*256 + k*ldB + n]
    const float* gB = Bg + (size_t)(b >> bshift) * 256 + n0 + c4;

    float acc[8][8];
#pragma unroll
    for (int i = 0; i < 8; i++)
#pragma unroll
        for (int j = 0; j < 8; j++) acc[i][j] = 0.f;

    for (int k0 = 0; k0 < 1024; k0 += 8) {
        float4 av = *(const float4*)(gA + k0);
        float4 bv = *(const float4*)(gB + (size_t)(k0 + r) * ldB);
        __syncthreads();
        As[lc + 0][lr] = av.x; As[lc + 1][lr] = av.y;
        As[lc + 2][lr] = av.z; As[lc + 3][lr] = av.w;
        *(float4*)&Bs[r][c4] = bv;
        __syncthreads();
#pragma unroll
        for (int k = 0; k < 8; k++) {
            float4 a0 = *(const float4*)&As[k][ty * 8];
            float4 a1 = *(const float4*)&As[k][ty * 8 + 4];
            float4 b0 = *(const float4*)&Bs[k][tx * 8];
            float4 b1v = *(const float4*)&Bs[k][tx * 8 + 4];
            float a[8]  = {a0.x, a0.y, a0.z, a0.w, a1.x, a1.y, a1.z, a1.w};
            float bb[8] = {b0.x, b0.y, b0.z, b0.w, b1v.x, b1v.y, b1v.z, b1v.w};
#pragma unroll
            for (int i = 0; i < 8; i++)
#pragma unroll
                for (int j = 0; j < 8; j++) acc[i][j] = fmaf(a[i], bb[j], acc[i][j]);
        }
    }
    float* C = Cg + (size_t)(m0 + ty * 8) * 32768 + (size_t)b * 256 + n0 + tx * 8;
#pragma unroll
    for (int i = 0; i < 8; i++) {
        float4 o0 = {acc[i][0], acc[i][1], acc[i][2], acc[i][3]};
        float4 o1 = {acc[i][4], acc[i][5], acc[i][6], acc[i][7]};
        *(float4*)(C + (size_t)i * 32768)     = o0;
        *(float4*)(C + (size_t)i * 32768 + 4) = o1;
    }
}

// ---------------------------------------------------------------------------
extern "C" void kernel_launch(void* const* d_in, const int* in_sizes, int n_in,
                              void* d_out, int out_size) {
    const float* query = (const float*)d_in[0];
    const float* node  = (const float*)d_in[1];
    const int*   maskq = (const int*)d_in[2];
    const int*   maskn = (const int*)d_in[3];

    float* out_ss = (float*)d_out;                        // [512,128,256]
    float* out_sq = out_ss + (size_t)512 * 128 * 256;     // [1024,128,256]
    float* out_cs = out_sq + (size_t)1024 * 128 * 256;    // [512,128,256]

    k_prod<<<dim3(8, 4, 128), 256>>>(query, node, maskq, maskn);
    k_colsoftmax<<<dim3(32, 128), dim3(32, 8)>>>();
    k_rowsoftmax<<<65536, 256>>>();
    k_outsq<<<dim3(2, 8, 128), 256>>>(node, out_sq);
    k_nn<<<dim3(2, 4, 128), 256>>>(query, 1024, 5, out_ss);
    k_nn<<<dim3(2, 4, 128), 256>>>(out_sq, 32768, 0, out_cs);
}

// round 6
// speedup vs baseline: 2.2959x; 2.2959x over previous
#include <cuda_runtime.h>
#include <cuda_bf16.h>
#include <math.h>
#include <stdint.h>

#define MIN_VAL (-99999999.0f)

// Shapes: query [1024,4,256] f32, node [512,128,256] f32, maskq [4,1024] i32, maskn [128,512] i32.
// Outputs: out_ss [512,128,256], out_sq [1024,128,256], cs [512,128,256] concatenated in d_out.

// ---------------- scratch (static device, allocation-rule compliant) ----------------
static __device__ float g_prod[67108864];   // [128][512][1024] scores -> wts1 in place
static __device__ float g_w2t[67108864];    // [128][1024][512] wts2 (t-major, s contiguous)
static __device__ float g_nodeT[16777216];  // [128][256][512] node transposed
static __device__ float g_queryT[1048576];  // [4][256][1024]  query transposed
static __device__ float g_osqT[33554432];   // [128][256][1024] out_sq transposed
static __device__ float g_colinv[131072];   // [128][1024] 1/colsum

// ---------------- helpers ----------------
__device__ __forceinline__ uint32_t smem_u32(const void* p) {
    uint32_t a;
    asm("{ .reg .u64 t; cvta.to.shared.u64 t, %1; cvt.u32.u64 %0, t; }" : "=r"(a) : "l"(p));
    return a;
}
__device__ __forceinline__ void ldsm4(uint32_t& r0, uint32_t& r1, uint32_t& r2, uint32_t& r3, uint32_t addr) {
    asm volatile("ldmatrix.sync.aligned.m8n8.x4.shared.b16 {%0,%1,%2,%3}, [%4];"
                 : "=r"(r0), "=r"(r1), "=r"(r2), "=r"(r3) : "r"(addr));
}
__device__ __forceinline__ void mma_bf16(float* d, const uint32_t* a, uint32_t b0, uint32_t b1) {
    asm volatile("mma.sync.aligned.m16n8k16.row.col.f32.bf16.bf16.f32 "
                 "{%0,%1,%2,%3}, {%4,%5,%6,%7}, {%8,%9}, {%0,%1,%2,%3};"
                 : "+f"(d[0]), "+f"(d[1]), "+f"(d[2]), "+f"(d[3])
                 : "r"(a[0]), "r"(a[1]), "r"(a[2]), "r"(a[3]), "r"(b0), "r"(b1));
}
// Split 2 floats into packed bf16 hi and bf16 lo (residual).
__device__ __forceinline__ void split2(float x, float y, uint32_t& hi, uint32_t& lo) {
    __nv_bfloat162 h = __float22bfloat162_rn(make_float2(x, y));
    float rx = x - __bfloat162float(h.x);
    float ry = y - __bfloat162float(h.y);
    __nv_bfloat162 l = __float22bfloat162_rn(make_float2(rx, ry));
    hi = *reinterpret_cast<uint32_t*>(&h);
    lo = *reinterpret_cast<uint32_t*>(&l);
}

// SMEM: [0..512) colmask, stages at 1024 + buf*40960; per stage: AH+0, AL+10240, BH+20480, BL+30720.
// Row stride = 80 bytes (64B data + 16B pad -> conflict-free ldmatrix phases).
#define ST_SZ   40960
#define SM_TOTAL (1024 + 2 * ST_SZ)

// ---------------------------------------------------------------------------
// Unified NT GEMM: D[128m x 128n] per CTA = A[m,k] . B[n,k]^T, bf16 split-2 x3 mma.sync.
// mode 0: mask+scale -> g_prod[b,s,t]; mode 1: -> g_osqT[b,d,t]; mode 2: -> Cout[(m0+m),b,d].
// ---------------------------------------------------------------------------
__global__ __launch_bounds__(256, 1) void k_mma(
    const float* __restrict__ query, const float* __restrict__ node,
    int asel, int aBoff, int aShift, int ldA,
    int bsel, int bBoff, int bShift, int ldB,
    int K, int mode, float* __restrict__ Cout,
    const int* __restrict__ maskq, const int* __restrict__ maskn) {
    extern __shared__ char smem[];
    const uint32_t sbase = smem_u32(smem);
    const int tid = threadIdx.x, wid = tid >> 5, l = tid & 31;
    const int b = blockIdx.z;
    const int n0 = blockIdx.x * 128;
    const int m0 = blockIdx.y * 128;
    const int NSt = K >> 5;

    const float* A0 = (asel == 0) ? node : (asel == 1) ? g_w2t : g_prod;
    const float* B0 = (bsel == 0) ? query : (bsel == 1) ? g_nodeT : (bsel == 2) ? g_queryT : g_osqT;
    const float* Ab = A0 + (size_t)(b >> aShift) * aBoff;
    const float* Bb = B0 + (size_t)(b >> bShift) * bBoff;

    int* colmask = (int*)smem;
    if (mode == 0 && tid < 128) colmask[tid] = maskq[(b >> 5) * 1024 + n0 + tid];

    const int wm = (wid & 1) * 64;    // warp m offset (2 warps)
    const int wn = (wid >> 1) * 32;   // warp n offset (4 warps)
    // ldmatrix per-lane row offsets
    const uint32_t a_off = (uint32_t)(l & 15) * 80u + ((uint32_t)(l >> 4) & 1u) * 16u;
    const uint32_t b_off = (uint32_t)((l & 7) + ((l >> 4) << 3)) * 80u + ((uint32_t)(l >> 3) & 1u) * 16u;

    float acc[4][4][4];
#pragma unroll
    for (int i = 0; i < 4; i++)
#pragma unroll
        for (int j = 0; j < 4; j++)
#pragma unroll
            for (int r = 0; r < 4; r++) acc[i][j][r] = 0.f;

    float4 va[2][2], vb[2][2];
    // prologue: load + store stage 0
#pragma unroll
    for (int it = 0; it < 2; it++) {
        int idx = tid + (it << 8); int r = idx >> 2, c = idx & 3;
        va[it][0] = *(const float4*)(Ab + (size_t)(m0 + r) * ldA + c * 8);
        va[it][1] = *(const float4*)(Ab + (size_t)(m0 + r) * ldA + c * 8 + 4);
        vb[it][0] = *(const float4*)(Bb + (size_t)(n0 + r) * ldB + c * 8);
        vb[it][1] = *(const float4*)(Bb + (size_t)(n0 + r) * ldB + c * 8 + 4);
    }
    {
        char* st = smem + 1024;
#pragma unroll
        for (int it = 0; it < 2; it++) {
            int idx = tid + (it << 8); int r = idx >> 2, c = idx & 3;
            uint32_t off = (uint32_t)r * 80u + (uint32_t)c * 16u;
            uint4 h, lo;
            split2(va[it][0].x, va[it][0].y, h.x, lo.x);
            split2(va[it][0].z, va[it][0].w, h.y, lo.y);
            split2(va[it][1].x, va[it][1].y, h.z, lo.z);
            split2(va[it][1].z, va[it][1].w, h.w, lo.w);
            *(uint4*)(st + off) = h;
            *(uint4*)(st + 10240 + off) = lo;
            split2(vb[it][0].x, vb[it][0].y, h.x, lo.x);
            split2(vb[it][0].z, vb[it][0].w, h.y, lo.y);
            split2(vb[it][1].x, vb[it][1].y, h.z, lo.z);
            split2(vb[it][1].z, vb[it][1].w, h.w, lo.w);
            *(uint4*)(st + 20480 + off) = h;
            *(uint4*)(st + 30720 + off) = lo;
        }
    }
    __syncthreads();

    for (int i = 0; i < NSt; i++) {
        if (i + 1 < NSt) {
            const int k0 = (i + 1) * 32;
#pragma unroll
            for (int it = 0; it < 2; it++) {
                int idx = tid + (it << 8); int r = idx >> 2, c = idx & 3;
                va[it][0] = *(const float4*)(Ab + (size_t)(m0 + r) * ldA + k0 + c * 8);
                va[it][1] = *(const float4*)(Ab + (size_t)(m0 + r) * ldA + k0 + c * 8 + 4);
                vb[it][0] = *(const float4*)(Bb + (size_t)(n0 + r) * ldB + k0 + c * 8);
                vb[it][1] = *(const float4*)(Bb + (size_t)(n0 + r) * ldB + k0 + c * 8 + 4);
            }
        }
        const uint32_t stg = sbase + 1024u + (uint32_t)(i & 1) * ST_SZ;
#pragma unroll
        for (int s = 0; s < 2; s++) {
            uint32_t ah[4][4], al[4][4], bh[4][2], bl[4][2];
#pragma unroll
            for (int mf = 0; mf < 4; mf++) {
                uint32_t ra = stg + (uint32_t)(wm + mf * 16) * 80u + a_off + (uint32_t)s * 32u;
                ldsm4(ah[mf][0], ah[mf][1], ah[mf][2], ah[mf][3], ra);
                ldsm4(al[mf][0], al[mf][1], al[mf][2], al[mf][3], ra + 10240u);
            }
#pragma unroll
            for (int p = 0; p < 2; p++) {
                uint32_t rb = stg + 20480u + (uint32_t)(wn + p * 16) * 80u + b_off + (uint32_t)s * 32u;
                uint32_t r0, r1, r2, r3;
                ldsm4(r0, r1, r2, r3, rb);
                bh[p * 2][0] = r0; bh[p * 2][1] = r1; bh[p * 2 + 1][0] = r2; bh[p * 2 + 1][1] = r3;
                ldsm4(r0, r1, r2, r3, rb + 10240u);
                bl[p * 2][0] = r0; bl[p * 2][1] = r1; bl[p * 2 + 1][0] = r2; bl[p * 2 + 1][1] = r3;
            }
#pragma unroll
            for (int mf = 0; mf < 4; mf++)
#pragma unroll
                for (int nf = 0; nf < 4; nf++) {
                    mma_bf16(acc[mf][nf], ah[mf], bh[nf][0], bh[nf][1]);
                    mma_bf16(acc[mf][nf], ah[mf], bl[nf][0], bl[nf][1]);
                    mma_bf16(acc[mf][nf], al[mf], bh[nf][0], bh[nf][1]);
                }
        }
        if (i + 1 < NSt) {
            char* st = smem + 1024 + ((i + 1) & 1) * ST_SZ;
#pragma unroll
            for (int it = 0; it < 2; it++) {
                int idx = tid + (it << 8); int r = idx >> 2, c = idx & 3;
                uint32_t off = (uint32_t)r * 80u + (uint32_t)c * 16u;
                uint4 h, lo;
                split2(va[it][0].x, va[it][0].y, h.x, lo.x);
                split2(va[it][0].z, va[it][0].w, h.y, lo.y);
                split2(va[it][1].x, va[it][1].y, h.z, lo.z);
                split2(va[it][1].z, va[it][1].w, h.w, lo.w);
                *(uint4*)(st + off) = h;
                *(uint4*)(st + 10240 + off) = lo;
                split2(vb[it][0].x, vb[it][0].y, h.x, lo.x);
                split2(vb[it][0].z, vb[it][0].w, h.y, lo.y);
                split2(vb[it][1].x, vb[it][1].y, h.z, lo.z);
                split2(vb[it][1].z, vb[it][1].w, h.w, lo.w);
                *(uint4*)(st + 20480 + off) = h;
                *(uint4*)(st + 30720 + off) = lo;
            }
            __syncthreads();
        }
    }

    // epilogue: lane holds rows (wm+mf*16 + l/4, +8), cols (wn+nf*8 + 2(l%4), +1)
    const int rb = l >> 2;
    const int cp = (l & 3) * 2;
    if (mode == 0) {
#pragma unroll
        for (int mf = 0; mf < 4; mf++) {
            const int gr = m0 + wm + mf * 16 + rb;
            const int rm0 = maskn[b * 512 + gr];
            const int rm1 = maskn[b * 512 + gr + 8];
            float* row0 = g_prod + ((size_t)b * 512 + gr) * 1024 + n0 + wn + cp;
#pragma unroll
            for (int nf = 0; nf < 4; nf++) {
                const int q0 = colmask[wn + nf * 8 + cp];
                const int q1 = colmask[wn + nf * 8 + cp + 1];
                float2 v0, v1;
                v0.x = (rm0 | q0) ? MIN_VAL : acc[mf][nf][0] * 0.0625f;
                v0.y = (rm0 | q1) ? MIN_VAL : acc[mf][nf][1] * 0.0625f;
                v1.x = (rm1 | q0) ? MIN_VAL : acc[mf][nf][2] * 0.0625f;
                v1.y = (rm1 | q1) ? MIN_VAL : acc[mf][nf][3] * 0.0625f;
                *(float2*)(row0 + nf * 8) = v0;
                *(float2*)(row0 + 8 * 1024 + nf * 8) = v1;
            }
        }
    } else if (mode == 1) {
        float* base = g_osqT + (size_t)b * 262144;
#pragma unroll
        for (int mf = 0; mf < 4; mf++) {
            const int t0 = m0 + wm + mf * 16 + rb;
#pragma unroll
            for (int nf = 0; nf < 4; nf++) {
                const int d0 = n0 + wn + nf * 8 + cp;
                base[(size_t)d0 * 1024 + t0] = acc[mf][nf][0];
                base[(size_t)(d0 + 1) * 1024 + t0] = acc[mf][nf][1];
                base[(size_t)d0 * 1024 + t0 + 8] = acc[mf][nf][2];
                base[(size_t)(d0 + 1) * 1024 + t0 + 8] = acc[mf][nf][3];
            }
        }
    } else {
#pragma unroll
        for (int mf = 0; mf < 4; mf++) {
            const int gr = m0 + wm + mf * 16 + rb;
            float* row0 = Cout + (size_t)gr * 32768 + (size_t)b * 256 + n0 + wn + cp;
#pragma unroll
            for (int nf = 0; nf < 4; nf++) {
                float2 v0 = {acc[mf][nf][0], acc[mf][nf][1]};
                float2 v1 = {acc[mf][nf][2], acc[mf][nf][3]};
                *(float2*)(row0 + nf * 8) = v0;
                *(float2*)(row0 + 8 * 32768 + nf * 8) = v1;
            }
        }
    }
}

// ---------------- aux kernels ----------------
__global__ __launch_bounds__(256) void k_colinv() { // 1/sum_s exp(prod[b,s,t])
    const int b = blockIdx.y;
    const int t = blockIdx.x * 256 + threadIdx.x;
    const float* P = g_prod + (size_t)b * 524288 + t;
    float L = 0.f;
    for (int s = 0; s < 512; s++) L += expf(P[(size_t)s * 1024]);
    g_colinv[b * 1024 + t] = (L > 0.f) ? 1.f / L : 0.f;
}

__global__ __launch_bounds__(256) void k_w2t() { // g_w2t[b,t,s] = exp(prod[b,s,t]) * colinv[b,t]
    __shared__ float tile[32][33];
    __shared__ float sinv[32];
    const int b = blockIdx.z, s0 = blockIdx.x * 32, t0 = blockIdx.y * 32;
    const int tx = threadIdx.x, ty = threadIdx.y;
    if (ty == 0) sinv[tx] = g_colinv[b * 1024 + t0 + tx];
#pragma unroll
    for (int i = 0; i < 4; i++) {
        int r = ty + i * 8;
        tile[r][tx] = expf(g_prod[(size_t)b * 524288 + (size_t)(s0 + r) * 1024 + t0 + tx]);
    }
    __syncthreads();
#pragma unroll
    for (int i = 0; i < 4; i++) {
        int r = ty + i * 8;
        g_w2t[(size_t)b * 524288 + (size_t)(t0 + r) * 512 + s0 + tx] = tile[tx][r] * sinv[r];
    }
}

__global__ __launch_bounds__(256) void k_rowsoftmax() { // wts1 in place on g_prod
    const size_t rowi = blockIdx.x;
    float* P = g_prod + rowi * 1024;
    const int tid = threadIdx.x;
    float4 v = *((const float4*)P + tid);
    float e0 = expf(v.x), e1 = expf(v.y), e2 = expf(v.z), e3 = expf(v.w);
    float s = e0 + e1 + e2 + e3;
#pragma unroll
    for (int o = 16; o; o >>= 1) s += __shfl_xor_sync(0xffffffffu, s, o);
    __shared__ float ssum[8];
    if ((tid & 31) == 0) ssum[tid >> 5] = s;
    __syncthreads();
    float S = 0.f;
#pragma unroll
    for (int i = 0; i < 8; i++) S += ssum[i];
    const float inv = (S > 0.f) ? 1.f / S : 0.f;
    v.x = e0 * inv; v.y = e1 * inv; v.z = e2 * inv; v.w = e3 * inv;
    *((float4*)P + tid) = v;
}

__global__ void k_tnode(const float* __restrict__ node) { // g_nodeT[b,d,s]
    __shared__ float tile[32][33];
    const int b = blockIdx.z, s0 = blockIdx.x * 32, d0 = blockIdx.y * 32;
    const int tx = threadIdx.x, ty = threadIdx.y;
#pragma unroll
    for (int i = 0; i < 4; i++) {
        int r = ty + i * 8;
        tile[r][tx] = node[(size_t)(s0 + r) * 32768 + (size_t)b * 256 + d0 + tx];
    }
    __syncthreads();
#pragma unroll
    for (int i = 0; i < 4; i++) {
        int r = ty + i * 8;
        g_nodeT[(size_t)b * 131072 + (size_t)(d0 + r) * 512 + s0 + tx] = tile[tx][r];
    }
}

__global__ void k_tquery(const float* __restrict__ query) { // g_queryT[b1,d,t]
    __shared__ float tile[32][33];
    const int b1 = blockIdx.z, t0 = blockIdx.x * 32, d0 = blockIdx.y * 32;
    const int tx = threadIdx.x, ty = threadIdx.y;
#pragma unroll
    for (int i = 0; i < 4; i++) {
        int r = ty + i * 8;
        tile[r][tx] = query[(size_t)(t0 + r) * 1024 + (size_t)b1 * 256 + d0 + tx];
    }
    __syncthreads();
#pragma unroll
    for (int i = 0; i < 4; i++) {
        int r = ty + i * 8;
        g_queryT[(size_t)b1 * 262144 + (size_t)(d0 + r) * 1024 + t0 + tx] = tile[tx][r];
    }
}

__global__ void k_tosq(float* __restrict__ out_sq) { // out_sq[t,b,d] from g_osqT[b,d,t]
    __shared__ float tile[32][33];
    const int b = blockIdx.z, t0 = blockIdx.x * 32, d0 = blockIdx.y * 32;
    const int tx = threadIdx.x, ty = threadIdx.y;
#pragma unroll
    for (int i = 0; i < 4; i++) {
        int r = ty + i * 8;
        tile[r][tx] = g_osqT[(size_t)b * 262144 + (size_t)(d0 + r) * 1024 + t0 + tx];
    }
    __syncthreads();
#pragma unroll
    for (int i = 0; i < 4; i++) {
        int r = ty + i * 8;
        out_sq[(size_t)(t0 + r) * 32768 + (size_t)b * 256 + d0 + tx] = tile[tx][r];
    }
}

// ---------------------------------------------------------------------------
extern "C" void kernel_launch(void* const* d_in, const int* in_sizes, int n_in,
                              void* d_out, int out_size) {
    const float* query = (const float*)d_in[0];
    const float* node  = (const float*)d_in[1];
    const int*   maskq = (const int*)d_in[2];
    const int*   maskn = (const int*)d_in[3];

    float* out_ss = (float*)d_out;
    float* out_sq = out_ss + (size_t)512 * 128 * 256;
    float* out_cs = out_sq + (size_t)1024 * 128 * 256;

    cudaFuncSetAttribute(k_mma, cudaFuncAttributeMaxDynamicSharedMemorySize, SM_TOTAL);

    // G1: scores -> g_prod (masked, scaled). A=node (ldA=32768), B=query (ldB=1024), K=256.
    k_mma<<<dim3(8, 4, 128), 256, SM_TOTAL>>>(query, node, 0, 256, 0, 32768,
                                              0, 256, 5, 1024, 256, 0, nullptr, maskq, maskn);
    k_colinv<<<dim3(4, 128), 256>>>();
    k_w2t<<<dim3(16, 32, 128), dim3(32, 8)>>>();
    k_rowsoftmax<<<65536, 256>>>();
    k_tnode<<<dim3(16, 8, 128), dim3(32, 8)>>>(node);
    k_tquery<<<dim3(32, 8, 4), dim3(32, 8)>>>(query);
    // G2: out_sqT[b,d,t]. A=g_w2t (ldA=512), B=g_nodeT (ldB=512), K=512, M=1024, N=256.
    k_mma<<<dim3(2, 8, 128), 256, SM_TOTAL>>>(query, node, 1, 524288, 0, 512,
                                              1, 131072, 0, 512, 512, 1, nullptr, maskq, maskn);
    k_tosq<<<dim3(32, 8, 128), dim3(32, 8)>>>(out_sq);
    // G3: out_ss. A=wts1 (ldA=1024), B=g_queryT (ldB=1024), K=1024, M=512, N=256.
    k_mma<<<dim3(2, 4, 128), 256, SM_TOTAL>>>(query, node, 2, 524288, 0, 1024,
                                              2, 262144, 5, 1024, 1024, 2, out_ss, maskq, maskn);
    // G4: cs. A=wts1, B=g_osqT (ldB=1024), K=1024.
    k_mma<<<dim3(2, 4, 128), 256, SM_TOTAL>>>(query, node, 2, 524288, 0, 1024,
                                              3, 262144, 0, 1024, 1024, 2, out_cs, maskq, maskn);
}

// round 7
// speedup vs baseline: 2.3561x; 1.0262x over previous
#include <cuda_runtime.h>
#include <cuda_bf16.h>
#include <math.h>
#include <stdint.h>

#define MIN_VAL (-99999999.0f)

// query [1024,4,256] f32, node [512,128,256] f32, maskq [4,1024] i32, maskn [128,512] i32.
// out: out_ss [512,128,256], out_sq [1024,128,256], cs [512,128,256].

// ---------------- scratch (static device) ----------------
static __device__ float g_prod[67108864];            // [128][512][1024] masked scores (fp32)
static __device__ __nv_bfloat16 g_w1H[67108864];     // wts1 hi  [b][s][t]
static __device__ __nv_bfloat16 g_w1L[67108864];     // wts1 lo
static __device__ __nv_bfloat16 g_w2tH[67108864];    // wts2 hi  [b][t][s]
static __device__ __nv_bfloat16 g_w2tL[67108864];
static __device__ __nv_bfloat16 g_nH[16777216];      // node hi  [b][s][d]
static __device__ __nv_bfloat16 g_nL[16777216];
static __device__ __nv_bfloat16 g_nTH[16777216];     // node hi  [b][d][s]
static __device__ __nv_bfloat16 g_nTL[16777216];
static __device__ __nv_bfloat16 g_qH[1048576];       // query hi [b1][t][d]
static __device__ __nv_bfloat16 g_qL[1048576];
static __device__ __nv_bfloat16 g_qTH[1048576];      // query hi [b1][d][t]
static __device__ __nv_bfloat16 g_qTL[1048576];
static __device__ __nv_bfloat16 g_osqTH[33554432];   // out_sq hi [b][d][t]
static __device__ __nv_bfloat16 g_osqTL[33554432];
static __device__ float g_colinv[131072];            // [128][1024]

// ---------------- helpers ----------------
__device__ __forceinline__ uint32_t smem_u32(const void* p) {
    uint32_t a;
    asm("{ .reg .u64 t; cvta.to.shared.u64 t, %1; cvt.u32.u64 %0, t; }" : "=r"(a) : "l"(p));
    return a;
}
__device__ __forceinline__ void ldsm4(uint32_t& r0, uint32_t& r1, uint32_t& r2, uint32_t& r3, uint32_t addr) {
    asm volatile("ldmatrix.sync.aligned.m8n8.x4.shared.b16 {%0,%1,%2,%3}, [%4];"
                 : "=r"(r0), "=r"(r1), "=r"(r2), "=r"(r3) : "r"(addr));
}
__device__ __forceinline__ void mma_bf16(float* d, const uint32_t* a, uint32_t b0, uint32_t b1) {
    asm volatile("mma.sync.aligned.m16n8k16.row.col.f32.bf16.bf16.f32 "
                 "{%0,%1,%2,%3}, {%4,%5,%6,%7}, {%8,%9}, {%0,%1,%2,%3};"
                 : "+f"(d[0]), "+f"(d[1]), "+f"(d[2]), "+f"(d[3])
                 : "r"(a[0]), "r"(a[1]), "r"(a[2]), "r"(a[3]), "r"(b0), "r"(b1));
}
__device__ __forceinline__ void splitf(float v, __nv_bfloat16& h, __nv_bfloat16& lo) {
    h = __float2bfloat16(v);
    lo = __float2bfloat16(v - __bfloat162float(h));
}
#define CP_ASYNC(dst, src) asm volatile("cp.async.cg.shared.global [%0], [%1], 16;" :: "r"(dst), "l"(src))
#define CP_COMMIT()        asm volatile("cp.async.commit_group;" ::: "memory")
#define CP_WAIT(n)         asm volatile("cp.async.wait_group %0;" :: "n"(n) : "memory")

// SMEM: [0..512) colmask; stages @1024 + s*40960; per stage AH+0 AL+10240 BH+20480 BL+30720.
// Row stride 80B (64B data + 16B pad): conflict-free ldmatrix phases.
#define ST_SZ 40960
#define SM_TOTAL (1024 + 2 * ST_SZ)

// ---------------------------------------------------------------------------
// NT GEMM, pre-split bf16 operands: D[128m x 128n] = A . B^T (3-term split-2).
// mode 0: mask+scale -> g_prod; mode 1: split-store -> g_osqTH/L[b][d][t]; mode 2: -> Cout[m][b][n].
// ---------------------------------------------------------------------------
__global__ __launch_bounds__(256, 2) void k_mma(
    int asel, int aBoff, int aShift, int ldA,
    int bsel, int bBoff, int bShift, int ldB,
    int K, int mode, float* __restrict__ Cout,
    const int* __restrict__ maskq, const int* __restrict__ maskn) {
    extern __shared__ char smem[];
    const uint32_t sbase = smem_u32(smem);
    const int tid = threadIdx.x, wid = tid >> 5, l = tid & 31;
    const int b = blockIdx.z;
    const int n0 = blockIdx.x * 128, m0 = blockIdx.y * 128;
    const int NSt = K >> 5;

    const __nv_bfloat16 *AH0, *AL0, *BH0, *BL0;
    if (asel == 0)      { AH0 = g_nH;   AL0 = g_nL;   }
    else if (asel == 1) { AH0 = g_w2tH; AL0 = g_w2tL; }
    else                { AH0 = g_w1H;  AL0 = g_w1L;  }
    if (bsel == 0)      { BH0 = g_qH;    BL0 = g_qL;    }
    else if (bsel == 1) { BH0 = g_nTH;   BL0 = g_nTL;   }
    else if (bsel == 2) { BH0 = g_qTH;   BL0 = g_qTL;   }
    else                { BH0 = g_osqTH; BL0 = g_osqTL; }
    const size_t aoff = (size_t)(b >> aShift) * aBoff + (size_t)m0 * ldA;
    const size_t boff = (size_t)(b >> bShift) * bBoff + (size_t)n0 * ldB;
    const __nv_bfloat16 *AH = AH0 + aoff, *AL = AL0 + aoff;
    const __nv_bfloat16 *BH = BH0 + boff, *BL = BL0 + boff;

    int* colmask = (int*)smem;
    if (mode == 0 && tid < 128) colmask[tid] = maskq[(b >> 5) * 1024 + n0 + tid];

    const int wm = (wid & 1) * 64;
    const int wn = (wid >> 1) * 32;
    const uint32_t a_off = (uint32_t)(l & 15) * 80u + ((uint32_t)(l >> 4) & 1u) * 16u;
    const uint32_t b_off = (uint32_t)((l & 7) + ((l >> 4) << 3)) * 80u + ((uint32_t)(l >> 3) & 1u) * 16u;

    float acc[4][4][4];
#pragma unroll
    for (int i = 0; i < 4; i++)
#pragma unroll
        for (int j = 0; j < 4; j++)
#pragma unroll
            for (int r = 0; r < 4; r++) acc[i][j][r] = 0.f;

    const int cr = tid >> 2, cc = tid & 3;  // cp.async: row base, 16B chunk
    // issue stage 0
    {
        uint32_t st = sbase + 1024u;
#pragma unroll
        for (int it = 0; it < 2; it++) {
            int r = cr + it * 64;
            uint32_t d = st + (uint32_t)r * 80u + (uint32_t)cc * 16u;
            CP_ASYNC(d,           AH + (size_t)r * ldA + cc * 8);
            CP_ASYNC(d + 10240u,  AL + (size_t)r * ldA + cc * 8);
            CP_ASYNC(d + 20480u,  BH + (size_t)r * ldB + cc * 8);
            CP_ASYNC(d + 30720u,  BL + (size_t)r * ldB + cc * 8);
        }
        CP_COMMIT();
    }

    for (int i = 0; i < NSt; i++) {
        if (i + 1 < NSt) {
            const int k0 = (i + 1) * 32;
            uint32_t st = sbase + 1024u + (uint32_t)((i + 1) & 1) * ST_SZ;
#pragma unroll
            for (int it = 0; it < 2; it++) {
                int r = cr + it * 64;
                uint32_t d = st + (uint32_t)r * 80u + (uint32_t)cc * 16u;
                CP_ASYNC(d,           AH + (size_t)r * ldA + k0 + cc * 8);
                CP_ASYNC(d + 10240u,  AL + (size_t)r * ldA + k0 + cc * 8);
                CP_ASYNC(d + 20480u,  BH + (size_t)r * ldB + k0 + cc * 8);
                CP_ASYNC(d + 30720u,  BL + (size_t)r * ldB + k0 + cc * 8);
            }
            CP_COMMIT();
            CP_WAIT(1);
        } else {
            CP_WAIT(0);
        }
        __syncthreads();

        const uint32_t stg = sbase + 1024u + (uint32_t)(i & 1) * ST_SZ;
#pragma unroll
        for (int s = 0; s < 2; s++) {
            uint32_t bh[4][2], bl[4][2];
#pragma unroll
            for (int p = 0; p < 2; p++) {
                uint32_t rbb = stg + 20480u + (uint32_t)(wn + p * 16) * 80u + b_off + (uint32_t)s * 32u;
                ldsm4(bh[p * 2][0], bh[p * 2][1], bh[p * 2 + 1][0], bh[p * 2 + 1][1], rbb);
                ldsm4(bl[p * 2][0], bl[p * 2][1], bl[p * 2 + 1][0], bl[p * 2 + 1][1], rbb + 10240u);
            }
#pragma unroll
            for (int mf = 0; mf < 4; mf++) {
                uint32_t ah[4], al[4];
                uint32_t raa = stg + (uint32_t)(wm + mf * 16) * 80u + a_off + (uint32_t)s * 32u;
                ldsm4(ah[0], ah[1], ah[2], ah[3], raa);
                ldsm4(al[0], al[1], al[2], al[3], raa + 10240u);
#pragma unroll
                for (int nf = 0; nf < 4; nf++) {
                    mma_bf16(acc[mf][nf], ah, bh[nf][0], bh[nf][1]);
                    mma_bf16(acc[mf][nf], ah, bl[nf][0], bl[nf][1]);
                    mma_bf16(acc[mf][nf], al, bh[nf][0], bh[nf][1]);
                }
            }
        }
        __syncthreads();
    }

    const int rb = l >> 2;
    const int cp = (l & 3) * 2;
    if (mode == 0) {
#pragma unroll
        for (int mf = 0; mf < 4; mf++) {
            const int gr = m0 + wm + mf * 16 + rb;
            const int rm0 = maskn[b * 512 + gr];
            const int rm1 = maskn[b * 512 + gr + 8];
            float* row0 = g_prod + ((size_t)b * 512 + gr) * 1024 + n0 + wn + cp;
#pragma unroll
            for (int nf = 0; nf < 4; nf++) {
                const int q0 = colmask[wn + nf * 8 + cp];
                const int q1 = colmask[wn + nf * 8 + cp + 1];
                float2 v0, v1;
                v0.x = (rm0 | q0) ? MIN_VAL : acc[mf][nf][0] * 0.0625f;
                v0.y = (rm0 | q1) ? MIN_VAL : acc[mf][nf][1] * 0.0625f;
                v1.x = (rm1 | q0) ? MIN_VAL : acc[mf][nf][2] * 0.0625f;
                v1.y = (rm1 | q1) ? MIN_VAL : acc[mf][nf][3] * 0.0625f;
                *(float2*)(row0 + nf * 8) = v0;
                *(float2*)(row0 + 8 * 1024 + nf * 8) = v1;
            }
        }
    } else if (mode == 1) {
        const size_t base = (size_t)b * 262144;
#pragma unroll
        for (int mf = 0; mf < 4; mf++) {
            const int t0 = m0 + wm + mf * 16 + rb;
#pragma unroll
            for (int nf = 0; nf < 4; nf++) {
                const int d0 = n0 + wn + nf * 8 + cp;
#pragma unroll
                for (int r = 0; r < 4; r++) {
                    const size_t idx = base + (size_t)(d0 + (r & 1)) * 1024 + t0 + (r >> 1) * 8;
                    __nv_bfloat16 h, lo;
                    splitf(acc[mf][nf][r], h, lo);
                    g_osqTH[idx] = h;
                    g_osqTL[idx] = lo;
                }
            }
        }
    } else {
#pragma unroll
        for (int mf = 0; mf < 4; mf++) {
            const int gr = m0 + wm + mf * 16 + rb;
            float* row0 = Cout + (size_t)gr * 32768 + (size_t)b * 256 + n0 + wn + cp;
#pragma unroll
            for (int nf = 0; nf < 4; nf++) {
                float2 v0 = {acc[mf][nf][0], acc[mf][nf][1]};
                float2 v1 = {acc[mf][nf][2], acc[mf][nf][3]};
                *(float2*)(row0 + nf * 8) = v0;
                *(float2*)(row0 + 8 * 32768 + nf * 8) = v1;
            }
        }
    }
}

// ---------------- producers / aux ----------------
__global__ void k_splitnode(const float* __restrict__ node) {
    __shared__ float tile[32][33];
    const int b = blockIdx.z, s0 = blockIdx.x * 32, d0 = blockIdx.y * 32;
    const int tx = threadIdx.x, ty = threadIdx.y;
#pragma unroll
    for (int i = 0; i < 4; i++) {
        int r = ty + i * 8;
        tile[r][tx] = node[(size_t)(s0 + r) * 32768 + (size_t)b * 256 + d0 + tx];
    }
    __syncthreads();
#pragma unroll
    for (int i = 0; i < 4; i++) {
        int r = ty + i * 8;
        __nv_bfloat16 h, lo;
        splitf(tile[r][tx], h, lo);
        size_t idx = (size_t)b * 131072 + (size_t)(s0 + r) * 256 + d0 + tx;
        g_nH[idx] = h; g_nL[idx] = lo;
        splitf(tile[tx][r], h, lo);
        idx = (size_t)b * 131072 + (size_t)(d0 + r) * 512 + s0 + tx;
        g_nTH[idx] = h; g_nTL[idx] = lo;
    }
}

__global__ void k_splitquery(const float* __restrict__ query) {
    __shared__ float tile[32][33];
    const int b1 = blockIdx.z, t0 = blockIdx.x * 32, d0 = blockIdx.y * 32;
    const int tx = threadIdx.x, ty = threadIdx.y;
#pragma unroll
    for (int i = 0; i < 4; i++) {
        int r = ty + i * 8;
        tile[r][tx] = query[(size_t)(t0 + r) * 1024 + (size_t)b1 * 256 + d0 + tx];
    }
    __syncthreads();
#pragma unroll
    for (int i = 0; i < 4; i++) {
        int r = ty + i * 8;
        __nv_bfloat16 h, lo;
        splitf(tile[r][tx], h, lo);
        size_t idx = (size_t)b1 * 262144 + (size_t)(t0 + r) * 256 + d0 + tx;
        g_qH[idx] = h; g_qL[idx] = lo;
        splitf(tile[tx][r], h, lo);
        idx = (size_t)b1 * 262144 + (size_t)(d0 + r) * 1024 + t0 + tx;
        g_qTH[idx] = h; g_qTL[idx] = lo;
    }
}

__global__ __launch_bounds__(256) void k_colinv() {
    const int b = blockIdx.y;
    const int t = blockIdx.x * 256 + threadIdx.x;
    const float* P = g_prod + (size_t)b * 524288 + t;
    float L = 0.f;
    for (int s = 0; s < 512; s++) L += expf(P[(size_t)s * 1024]);
    g_colinv[b * 1024 + t] = (L > 0.f) ? 1.f / L : 0.f;
}

__global__ void k_w2t() { // w2tH/L[b][t][s] = split(exp(prod[b,s,t]) * colinv[b,t])
    __shared__ float tile[32][33];
    __shared__ float sinv[32];
    const int b = blockIdx.z, s0 = blockIdx.x * 32, t0 = blockIdx.y * 32;
    const int tx = threadIdx.x, ty = threadIdx.y;
    if (ty == 0) sinv[tx] = g_colinv[b * 1024 + t0 + tx];
#pragma unroll
    for (int i = 0; i < 4; i++) {
        int r = ty + i * 8;
        tile[r][tx] = expf(g_prod[(size_t)b * 524288 + (size_t)(s0 + r) * 1024 + t0 + tx]);
    }
    __syncthreads();
#pragma unroll
    for (int i = 0; i < 4; i++) {
        int r = ty + i * 8;
        __nv_bfloat16 h, lo;
        splitf(tile[tx][r] * sinv[r], h, lo);
        size_t idx = (size_t)b * 524288 + (size_t)(t0 + r) * 512 + s0 + tx;
        g_w2tH[idx] = h; g_w2tL[idx] = lo;
    }
}

__global__ __launch_bounds__(256) void k_rowsoftmax() { // w1H/L[b][s][t] from g_prod
    const size_t rowi = blockIdx.x;
    const float* P = g_prod + rowi * 1024;
    const int tid = threadIdx.x;
    float4 v = *((const float4*)P + tid);
    float e0 = expf(v.x), e1 = expf(v.y), e2 = expf(v.z), e3 = expf(v.w);
    float s = e0 + e1 + e2 + e3;
#pragma unroll
    for (int o = 16; o; o >>= 1) s += __shfl_xor_sync(0xffffffffu, s, o);
    __shared__ float ssum[8];
    if ((tid & 31) == 0) ssum[tid >> 5] = s;
    __syncthreads();
    float S = 0.f;
#pragma unroll
    for (int i = 0; i < 8; i++) S += ssum[i];
    const float inv = (S > 0.f) ? 1.f / S : 0.f;
    float w[4] = {e0 * inv, e1 * inv, e2 * inv, e3 * inv};
    __nv_bfloat16 h[4], lo[4];
#pragma unroll
    for (int i = 0; i < 4; i++) splitf(w[i], h[i], lo[i]);
    *(uint2*)(g_w1H + rowi * 1024 + tid * 4) = *(uint2*)h;
    *(uint2*)(g_w1L + rowi * 1024 + tid * 4) = *(uint2*)lo;
}

__global__ void k_tosq(float* __restrict__ out_sq) { // out_sq[t,b,d] = hi+lo from osqTH/L[b][d][t]
    __shared__ float tile[32][33];
    const int b = blockIdx.z, t0 = blockIdx.x * 32, d0 = blockIdx.y * 32;
    const int tx = threadIdx.x, ty = threadIdx.y;
#pragma unroll
    for (int i = 0; i < 4; i++) {
        int r = ty + i * 8;
        size_t idx = (size_t)b * 262144 + (size_t)(d0 + r) * 1024 + t0 + tx;
        tile[r][tx] = __bfloat162float(g_osqTH[idx]) + __bfloat162float(g_osqTL[idx]);
    }
    __syncthreads();
#pragma unroll
    for (int i = 0; i < 4; i++) {
        int r = ty + i * 8;
        out_sq[(size_t)(t0 + r) * 32768 + (size_t)b * 256 + d0 + tx] = tile[tx][r];
    }
}

// ---------------------------------------------------------------------------
extern "C" void kernel_launch(void* const* d_in, const int* in_sizes, int n_in,
                              void* d_out, int out_size) {
    const float* query = (const float*)d_in[0];
    const float* node  = (const float*)d_in[1];
    const int*   maskq = (const int*)d_in[2];
    const int*   maskn = (const int*)d_in[3];

    float* out_ss = (float*)d_out;
    float* out_sq = out_ss + (size_t)512 * 128 * 256;
    float* out_cs = out_sq + (size_t)1024 * 128 * 256;

    cudaFuncSetAttribute(k_mma, cudaFuncAttributeMaxDynamicSharedMemorySize, SM_TOTAL);

    k_splitnode<<<dim3(16, 8, 128), dim3(32, 8)>>>(node);
    k_splitquery<<<dim3(32, 8, 4), dim3(32, 8)>>>(query);
    // G1: prod = node . query^T (masked, scaled). A=nH/L[b] ld256, B=qH/L[b>>5] ld256, K=256.
    k_mma<<<dim3(8, 4, 128), 256, SM_TOTAL>>>(0, 131072, 0, 256,
                                              0, 262144, 5, 256, 256, 0, nullptr, maskq, maskn);
    k_colinv<<<dim3(4, 128), 256>>>();
    k_w2t<<<dim3(16, 32, 128), dim3(32, 8)>>>();
    k_rowsoftmax<<<65536, 256>>>();
    // G2: osqT[b][d][t] = w2t . nodeT^T. A=w2tH/L ld512, B=nTH/L ld512, K=512, M=1024, N=256.
    k_mma<<<dim3(2, 8, 128), 256, SM_TOTAL>>>(1, 524288, 0, 512,
                                              1, 131072, 0, 512, 512, 1, nullptr, maskq, maskn);
    k_tosq<<<dim3(32, 8, 128), dim3(32, 8)>>>(out_sq);
    // G3: out_ss = w1 . qT^T. A=w1H/L ld1024, B=qTH/L[b>>5] ld1024, K=1024, M=512, N=256.
    k_mma<<<dim3(2, 4, 128), 256, SM_TOTAL>>>(2, 524288, 0, 1024,
                                              2, 262144, 5, 1024, 1024, 2, out_ss, maskq, maskn);
    // G4: cs = w1 . osqT^T. B=osqTH/L ld1024.
    k_mma<<<dim3(2, 4, 128), 256, SM_TOTAL>>>(2, 524288, 0, 1024,
                                              3, 262144, 0, 1024, 1024, 2, out_cs, maskq, maskn);
}

// round 10
// speedup vs baseline: 2.8640x; 1.2156x over previous
#include <cuda_runtime.h>
#include <cuda_fp16.h>
#include <math.h>
#include <stdint.h>

#define MIN_VAL (-99999999.0f)

// query [1024,4,256] f32, node [512,128,256] f32, maskq [4,1024] i32, maskn [128,512] i32.
// out: out_ss [512,128,256], out_sq [1024,128,256], cs [512,128,256].

// ---------------- scratch (static device) ----------------
static __device__ float g_prod[67108864];       // [128][512][1024] masked scores (fp32)
static __device__ __half g_w1H[67108864];       // wts1 hi  [b][s][t]  (no lo: 2-term GEMMs)
static __device__ __half g_w2tH[67108864];      // wts2 hi  [b][t][s]
static __device__ __half g_nH[16777216];        // node hi  [b][s][d]
static __device__ __half g_nL[16777216];
static __device__ __half g_nTH[16777216];       // node hi  [b][d][s]
static __device__ __half g_nTL[16777216];
static __device__ __half g_qH[1048576];         // query hi [b1][t][d]
static __device__ __half g_qL[1048576];
static __device__ __half g_qTH[1048576];        // query hi [b1][d][t]
static __device__ __half g_qTL[1048576];
static __device__ __half g_osqTH[33554432];     // out_sq hi [b][d][t]
static __device__ __half g_osqTL[33554432];
static __device__ float g_colinv[131072];       // [128][1024]

// ---------------- helpers ----------------
__device__ __forceinline__ uint32_t smem_u32(const void* p) {
    uint32_t a;
    asm("{ .reg .u64 t; cvta.to.shared.u64 t, %1; cvt.u32.u64 %0, t; }" : "=r"(a) : "l"(p));
    return a;
}
__device__ __forceinline__ void ldsm4(uint32_t& r0, uint32_t& r1, uint32_t& r2, uint32_t& r3, uint32_t addr) {
    asm volatile("ldmatrix.sync.aligned.m8n8.x4.shared.b16 {%0,%1,%2,%3}, [%4];"
                 : "=r"(r0), "=r"(r1), "=r"(r2), "=r"(r3) : "r"(addr));
}
__device__ __forceinline__ void mma_f16(float* d, const uint32_t* a, uint32_t b0, uint32_t b1) {
    asm volatile("mma.sync.aligned.m16n8k16.row.col.f32.f16.f16.f32 "
                 "{%0,%1,%2,%3}, {%4,%5,%6,%7}, {%8,%9}, {%0,%1,%2,%3};"
                 : "+f"(d[0]), "+f"(d[1]), "+f"(d[2]), "+f"(d[3])
                 : "r"(a[0]), "r"(a[1]), "r"(a[2]), "r"(a[3]), "r"(b0), "r"(b1));
}
__device__ __forceinline__ void splitf(float v, __half& h, __half& lo) {
    h = __float2half_rn(v);
    lo = __float2half_rn(v - __half2float(h));
}
#define CP_ASYNC(dst, src) asm volatile("cp.async.cg.shared.global [%0], [%1], 16;" :: "r"(dst), "l"(src))
#define CP_COMMIT()        asm volatile("cp.async.commit_group;" ::: "memory")
#define CP_WAIT(n)         asm volatile("cp.async.wait_group %0;" :: "n"(n) : "memory")

// SMEM: [0..512) colmask; stages @1024 + s*40960; per stage AH+0 AL+10240 BH+20480 BL+30720.
// Row stride 80B (64B data + 16B pad): conflict-free ldmatrix phases.
#define ST_SZ 40960
#define SM_TOTAL (1024 + 2 * ST_SZ)

// ---------------------------------------------------------------------------
// NT GEMM, pre-split fp16 operands: D[128m x 128n] = A . B^T.
// TERMS==3: ah*bh + ah*bl + al*bh (G1). TERMS==2: ah*bh + ah*bl (A-lo never touched).
// mode 0: mask+scale -> g_prod; mode 1: split-store -> g_osqTH/L[b][d][t]; mode 2: -> Cout[m][b][n].
// ---------------------------------------------------------------------------
template <int TERMS>
__global__ __launch_bounds__(256, 2) void k_mma(
    int asel, int aBoff, int aShift, int ldA,
    int bsel, int bBoff, int bShift, int ldB,
    int K, int mode, float* __restrict__ Cout,
    const int* __restrict__ maskq, const int* __restrict__ maskn) {
    extern __shared__ char smem[];
    const uint32_t sbase = smem_u32(smem);
    const int tid = threadIdx.x, wid = tid >> 5, l = tid & 31;
    const int b = blockIdx.z;
    const int n0 = blockIdx.x * 128, m0 = blockIdx.y * 128;
    const int NSt = K >> 5;
    constexpr bool three = (TERMS == 3);

    const __half *AH0, *AL0, *BH0, *BL0;
    if (asel == 0)      { AH0 = g_nH;   AL0 = g_nL; }
    else if (asel == 1) { AH0 = g_w2tH; AL0 = g_w2tH; }  // lo unused (2-term)
    else                { AH0 = g_w1H;  AL0 = g_w1H;  }  // lo unused
    if (bsel == 0)      { BH0 = g_qH;    BL0 = g_qL;    }
    else if (bsel == 1) { BH0 = g_nTH;   BL0 = g_nTL;   }
    else if (bsel == 2) { BH0 = g_qTH;   BL0 = g_qTL;   }
    else                { BH0 = g_osqTH; BL0 = g_osqTL; }
    const size_t aoff = (size_t)(b >> aShift) * aBoff + (size_t)m0 * ldA;
    const size_t boff = (size_t)(b >> bShift) * bBoff + (size_t)n0 * ldB;
    const __half *AH = AH0 + aoff, *AL = AL0 + aoff;
    const __half *BH = BH0 + boff, *BL = BL0 + boff;

    int* colmask = (int*)smem;
    if (mode == 0 && tid < 128) colmask[tid] = maskq[(b >> 5) * 1024 + n0 + tid];

    const int wm = (wid & 1) * 64;
    const int wn = (wid >> 1) * 32;
    const uint32_t a_off = (uint32_t)(l & 15) * 80u + ((uint32_t)(l >> 4) & 1u) * 16u;
    const uint32_t b_off = (uint32_t)((l & 7) + ((l >> 4) << 3)) * 80u + ((uint32_t)(l >> 3) & 1u) * 16u;

    float acc[4][4][4];
#pragma unroll
    for (int i = 0; i < 4; i++)
#pragma unroll
        for (int j = 0; j < 4; j++)
#pragma unroll
            for (int r = 0; r < 4; r++) acc[i][j][r] = 0.f;

    const int cr = tid >> 2, cc = tid & 3;
    {
        uint32_t st = sbase + 1024u;
#pragma unroll
        for (int it = 0; it < 2; it++) {
            int r = cr + it * 64;
            uint32_t d = st + (uint32_t)r * 80u + (uint32_t)cc * 16u;
            CP_ASYNC(d,           AH + (size_t)r * ldA + cc * 8);
            if (three) CP_ASYNC(d + 10240u, AL + (size_t)r * ldA + cc * 8);
            CP_ASYNC(d + 20480u,  BH + (size_t)r * ldB + cc * 8);
            CP_ASYNC(d + 30720u,  BL + (size_t)r * ldB + cc * 8);
        }
        CP_COMMIT();
    }

    for (int i = 0; i < NSt; i++) {
        if (i + 1 < NSt) {
            const int k0 = (i + 1) * 32;
            uint32_t st = sbase + 1024u + (uint32_t)((i + 1) & 1) * ST_SZ;
#pragma unroll
            for (int it = 0; it < 2; it++) {
                int r = cr + it * 64;
                uint32_t d = st + (uint32_t)r * 80u + (uint32_t)cc * 16u;
                CP_ASYNC(d,           AH + (size_t)r * ldA + k0 + cc * 8);
                if (three) CP_ASYNC(d + 10240u, AL + (size_t)r * ldA + k0 + cc * 8);
                CP_ASYNC(d + 20480u,  BH + (size_t)r * ldB + k0 + cc * 8);
                CP_ASYNC(d + 30720u,  BL + (size_t)r * ldB + k0 + cc * 8);
            }
            CP_COMMIT();
            CP_WAIT(1);
        } else {
            CP_WAIT(0);
        }
        __syncthreads();

        const uint32_t stg = sbase + 1024u + (uint32_t)(i & 1) * ST_SZ;
#pragma unroll
        for (int s = 0; s < 2; s++) {
            uint32_t bh[4][2], bl[4][2];
#pragma unroll
            for (int p = 0; p < 2; p++) {
                uint32_t rbb = stg + 20480u + (uint32_t)(wn + p * 16) * 80u + b_off + (uint32_t)s * 32u;
                ldsm4(bh[p * 2][0], bh[p * 2][1], bh[p * 2 + 1][0], bh[p * 2 + 1][1], rbb);
                ldsm4(bl[p * 2][0], bl[p * 2][1], bl[p * 2 + 1][0], bl[p * 2 + 1][1], rbb + 10240u);
            }
#pragma unroll
            for (int mf = 0; mf < 4; mf++) {
                uint32_t ah[4], al[4];
                uint32_t raa = stg + (uint32_t)(wm + mf * 16) * 80u + a_off + (uint32_t)s * 32u;
                ldsm4(ah[0], ah[1], ah[2], ah[3], raa);
                if (three) ldsm4(al[0], al[1], al[2], al[3], raa + 10240u);
#pragma unroll
                for (int nf = 0; nf < 4; nf++) {
                    mma_f16(acc[mf][nf], ah, bh[nf][0], bh[nf][1]);
                    mma_f16(acc[mf][nf], ah, bl[nf][0], bl[nf][1]);
                    if (three) mma_f16(acc[mf][nf], al, bh[nf][0], bh[nf][1]);
                }
            }
        }
        __syncthreads();
    }

    const int rb = l >> 2;
    const int cp = (l & 3) * 2;
    if (mode == 0) {
#pragma unroll
        for (int mf = 0; mf < 4; mf++) {
            const int gr = m0 + wm + mf * 16 + rb;
            const int rm0 = maskn[b * 512 + gr];
            const int rm1 = maskn[b * 512 + gr + 8];
            float* row0 = g_prod + ((size_t)b * 512 + gr) * 1024 + n0 + wn + cp;
#pragma unroll
            for (int nf = 0; nf < 4; nf++) {
                const int q0 = colmask[wn + nf * 8 + cp];
                const int q1 = colmask[wn + nf * 8 + cp + 1];
                float2 v0, v1;
                v0.x = (rm0 | q0) ? MIN_VAL : acc[mf][nf][0] * 0.0625f;
                v0.y = (rm0 | q1) ? MIN_VAL : acc[mf][nf][1] * 0.0625f;
                v1.x = (rm1 | q0) ? MIN_VAL : acc[mf][nf][2] * 0.0625f;
                v1.y = (rm1 | q1) ? MIN_VAL : acc[mf][nf][3] * 0.0625f;
                *(float2*)(row0 + nf * 8) = v0;
                *(float2*)(row0 + 8 * 1024 + nf * 8) = v1;
            }
        }
    } else if (mode == 1) {
        const size_t base = (size_t)b * 262144;
#pragma unroll
        for (int mf = 0; mf < 4; mf++) {
            const int t0 = m0 + wm + mf * 16 + rb;
#pragma unroll
            for (int nf = 0; nf < 4; nf++) {
                const int d0 = n0 + wn + nf * 8 + cp;
#pragma unroll
                for (int r = 0; r < 4; r++) {
                    const size_t idx = base + (size_t)(d0 + (r & 1)) * 1024 + t0 + (r >> 1) * 8;
                    __half h, lo;
                    splitf(acc[mf][nf][r], h, lo);
                    g_osqTH[idx] = h;
                    g_osqTL[idx] = lo;
                }
            }
        }
    } else {
#pragma unroll
        for (int mf = 0; mf < 4; mf++) {
            const int gr = m0 + wm + mf * 16 + rb;
            float* row0 = Cout + (size_t)gr * 32768 + (size_t)b * 256 + n0 + wn + cp;
#pragma unroll
            for (int nf = 0; nf < 4; nf++) {
                float2 v0 = {acc[mf][nf][0], acc[mf][nf][1]};
                float2 v1 = {acc[mf][nf][2], acc[mf][nf][3]};
                *(float2*)(row0 + nf * 8) = v0;
                *(float2*)(row0 + 8 * 32768 + nf * 8) = v1;
            }
        }
    }
}

// ---------------- producers / aux ----------------
__global__ void k_splitnode(const float* __restrict__ node) {
    __shared__ float tile[32][33];
    const int b = blockIdx.z, s0 = blockIdx.x * 32, d0 = blockIdx.y * 32;
    const int tx = threadIdx.x, ty = threadIdx.y;
#pragma unroll
    for (int i = 0; i < 4; i++) {
        int r = ty + i * 8;
        tile[r][tx] = node[(size_t)(s0 + r) * 32768 + (size_t)b * 256 + d0 + tx];
    }
    __syncthreads();
#pragma unroll
    for (int i = 0; i < 4; i++) {
        int r = ty + i * 8;
        __half h, lo;
        splitf(tile[r][tx], h, lo);
        size_t idx = (size_t)b * 131072 + (size_t)(s0 + r) * 256 + d0 + tx;
        g_nH[idx] = h; g_nL[idx] = lo;
        splitf(tile[tx][r], h, lo);
        idx = (size_t)b * 131072 + (size_t)(d0 + r) * 512 + s0 + tx;
        g_nTH[idx] = h; g_nTL[idx] = lo;
    }
}

__global__ void k_splitquery(const float* __restrict__ query) {
    __shared__ float tile[32][33];
    const int b1 = blockIdx.z, t0 = blockIdx.x * 32, d0 = blockIdx.y * 32;
    const int tx = threadIdx.x, ty = threadIdx.y;
#pragma unroll
    for (int i = 0; i < 4; i++) {
        int r = ty + i * 8;
        tile[r][tx] = query[(size_t)(t0 + r) * 1024 + (size_t)b1 * 256 + d0 + tx];
    }
    __syncthreads();
#pragma unroll
    for (int i = 0; i < 4; i++) {
        int r = ty + i * 8;
        __half h, lo;
        splitf(tile[r][tx], h, lo);
        size_t idx = (size_t)b1 * 262144 + (size_t)(t0 + r) * 256 + d0 + tx;
        g_qH[idx] = h; g_qL[idx] = lo;
        splitf(tile[tx][r], h, lo);
        idx = (size_t)b1 * 262144 + (size_t)(d0 + r) * 1024 + t0 + tx;
        g_qTH[idx] = h; g_qTL[idx] = lo;
    }
}

__global__ __launch_bounds__(256) void k_colinv() {
    const int b = blockIdx.y;
    const int t = blockIdx.x * 256 + threadIdx.x;
    const float* P = g_prod + (size_t)b * 524288 + t;
    float L = 0.f;
    for (int s = 0; s < 512; s++) L += expf(P[(size_t)s * 1024]);
    g_colinv[b * 1024 + t] = (L > 0.f) ? 1.f / L : 0.f;
}

__global__ void k_w2t() { // w2tH[b][t][s] = fp16(exp(prod[b,s,t]) * colinv[b,t])
    __shared__ float tile[32][33];
    __shared__ float sinv[32];
    const int b = blockIdx.z, s0 = blockIdx.x * 32, t0 = blockIdx.y * 32;
    const int tx = threadIdx.x, ty = threadIdx.y;
    if (ty == 0) sinv[tx] = g_colinv[b * 1024 + t0 + tx];
#pragma unroll
    for (int i = 0; i < 4; i++) {
        int r = ty + i * 8;
        tile[r][tx] = expf(g_prod[(size_t)b * 524288 + (size_t)(s0 + r) * 1024 + t0 + tx]);
    }
    __syncthreads();
#pragma unroll
    for (int i = 0; i < 4; i++) {
        int r = ty + i * 8;
        g_w2tH[(size_t)b * 524288 + (size_t)(t0 + r) * 512 + s0 + tx] =
            __float2half_rn(tile[tx][r] * sinv[r]);
    }
}

__global__ __launch_bounds__(256) void k_rowsoftmax() { // w1H[b][s][t] from g_prod
    const size_t rowi = blockIdx.x;
    const float* P = g_prod + rowi * 1024;
    const int tid = threadIdx.x;
    float4 v = *((const float4*)P + tid);
    float e0 = expf(v.x), e1 = expf(v.y), e2 = expf(v.z), e3 = expf(v.w);
    float s = e0 + e1 + e2 + e3;
#pragma unroll
    for (int o = 16; o; o >>= 1) s += __shfl_xor_sync(0xffffffffu, s, o);
    __shared__ float ssum[8];
    if ((tid & 31) == 0) ssum[tid >> 5] = s;
    __syncthreads();
    float S = 0.f;
#pragma unroll
    for (int i = 0; i < 8; i++) S += ssum[i];
    const float inv = (S > 0.f) ? 1.f / S : 0.f;
    __half h[4] = {__float2half_rn(e0 * inv), __float2half_rn(e1 * inv),
                   __float2half_rn(e2 * inv), __float2half_rn(e3 * inv)};
    *(uint2*)(g_w1H + rowi * 1024 + tid * 4) = *(uint2*)h;
}

__global__ void k_tosq(float* __restrict__ out_sq) { // out_sq[t,b,d] = hi+lo from osqTH/L[b][d][t]
    __shared__ float tile[32][33];
    const int b = blockIdx.z, t0 = blockIdx.x * 32, d0 = blockIdx.y * 32;
    const int tx = threadIdx.x, ty = threadIdx.y;
#pragma unroll
    for (int i = 0; i < 4; i++) {
        int r = ty + i * 8;
        size_t idx = (size_t)b * 262144 + (size_t)(d0 + r) * 1024 + t0 + tx;
        tile[r][tx] = __half2float(g_osqTH[idx]) + __half2float(g_osqTL[idx]);
    }
    __syncthreads();
#pragma unroll
    for (int i = 0; i < 4; i++) {
        int r = ty + i * 8;
        out_sq[(size_t)(t0 + r) * 32768 + (size_t)b * 256 + d0 + tx] = tile[tx][r];
    }
}

// ---------------------------------------------------------------------------
extern "C" void kernel_launch(void* const* d_in, const int* in_sizes, int n_in,
                              void* d_out, int out_size) {
    const float* query = (const float*)d_in[0];
    const float* node  = (const float*)d_in[1];
    const int*   maskq = (const int*)d_in[2];
    const int*   maskn = (const int*)d_in[3];

    float* out_ss = (float*)d_out;
    float* out_sq = out_ss + (size_t)512 * 128 * 256;
    float* out_cs = out_sq + (size_t)1024 * 128 * 256;

    cudaFuncSetAttribute(k_mma<3>, cudaFuncAttributeMaxDynamicSharedMemorySize, SM_TOTAL);
    cudaFuncSetAttribute(k_mma<2>, cudaFuncAttributeMaxDynamicSharedMemorySize, SM_TOTAL);

    k_splitnode<<<dim3(16, 8, 128), dim3(32, 8)>>>(node);
    k_splitquery<<<dim3(32, 8, 4), dim3(32, 8)>>>(query);
    // G1 (3-term): prod = node . query^T. A=nH/L ld256, B=qH/L[b>>5] ld256, K=256.
    k_mma<3><<<dim3(8, 4, 128), 256, SM_TOTAL>>>(0, 131072, 0, 256,
                                                 0, 262144, 5, 256, 256, 0, nullptr, maskq, maskn);
    k_colinv<<<dim3(4, 128), 256>>>();
    k_w2t<<<dim3(16, 32, 128), dim3(32, 8)>>>();
    k_rowsoftmax<<<65536, 256>>>();
    // G2 (2-term): osqT[b][d][t] = w2t . nodeT^T. K=512, M=1024, N=256.
    k_mma<2><<<dim3(2, 8, 128), 256, SM_TOTAL>>>(1, 524288, 0, 512,
                                                 1, 131072, 0, 512, 512, 1, nullptr, maskq, maskn);
    k_tosq<<<dim3(32, 8, 128), dim3(32, 8)>>>(out_sq);
    // G3 (2-term): out_ss = w1 . qT^T. K=1024, M=512, N=256.
    k_mma<2><<<dim3(2, 4, 128), 256, SM_TOTAL>>>(2, 524288, 0, 1024,
                                                 2, 262144, 5, 1024, 1024, 2, out_ss, maskq, maskn);
    // G4 (2-term): cs = w1 . osqT^T.
    k_mma<2><<<dim3(2, 4, 128), 256, SM_TOTAL>>>(2, 524288, 0, 1024,
                                                 3, 262144, 0, 1024, 1024, 2, out_cs, maskq, maskn);
}

// round 12
// speedup vs baseline: 3.5111x; 1.2259x over previous
#include <cuda_runtime.h>
#include <cuda_fp16.h>
#include <math.h>
#include <stdint.h>

#define MIN_VAL (-99999999.0f)

// query [1024,4,256] f32, node [512,128,256] f32, maskq [4,1024] i32, maskn [128,512] i32.
// out: out_ss [512,128,256], out_sq [1024,128,256], cs [512,128,256].

// ---------------- scratch (static device) ----------------
static __device__ float g_prod[67108864];       // [128][512][1024] masked scores (fp32)
static __device__ __half g_w1H[67108864];       // wts1 hi  [b][s][t]
static __device__ __half g_w2tH[67108864];      // wts2 hi  [b][t][s]
static __device__ __half g_nH[16777216];        // node hi  [b][s][d]
static __device__ __half g_nL[16777216];
static __device__ __half g_nTH[16777216];       // node hi  [b][d][s]
static __device__ __half g_nTL[16777216];
static __device__ __half g_qH[1048576];         // query hi [b1][t][d]
static __device__ __half g_qL[1048576];
static __device__ __half g_qTH[1048576];        // query hi [b1][d][t]
static __device__ __half g_qTL[1048576];
static __device__ __half g_osqTH[33554432];     // out_sq hi [b][d][t]
static __device__ __half g_osqTL[33554432];
static __device__ float g_colinv[131072];       // [128][1024]

// ---------------- helpers ----------------
__device__ __forceinline__ uint32_t smem_u32(const void* p) {
    uint32_t a;
    asm("{ .reg .u64 t; cvta.to.shared.u64 t, %1; cvt.u32.u64 %0, t; }" : "=r"(a) : "l"(p));
    return a;
}
__device__ __forceinline__ void ldsm4(uint32_t& r0, uint32_t& r1, uint32_t& r2, uint32_t& r3, uint32_t addr) {
    asm volatile("ldmatrix.sync.aligned.m8n8.x4.shared.b16 {%0,%1,%2,%3}, [%4];"
                 : "=r"(r0), "=r"(r1), "=r"(r2), "=r"(r3) : "r"(addr));
}
__device__ __forceinline__ void mma_f16(float* d, const uint32_t* a, uint32_t b0, uint32_t b1) {
    asm volatile("mma.sync.aligned.m16n8k16.row.col.f32.f16.f16.f32 "
                 "{%0,%1,%2,%3}, {%4,%5,%6,%7}, {%8,%9}, {%0,%1,%2,%3};"
                 : "+f"(d[0]), "+f"(d[1]), "+f"(d[2]), "+f"(d[3])
                 : "r"(a[0]), "r"(a[1]), "r"(a[2]), "r"(a[3]), "r"(b0), "r"(b1));
}
__device__ __forceinline__ void splitf(float v, __half& h, __half& lo) {
    h = __float2half_rn(v);
    lo = __float2half_rn(v - __half2float(h));
}
#define CP_ASYNC(dst, src) asm volatile("cp.async.cg.shared.global [%0], [%1], 16;" :: "r"(dst), "l"(src))
#define CP_COMMIT()        asm volatile("cp.async.commit_group;" ::: "memory")
#define CP_WAIT(n)         asm volatile("cp.async.wait_group %0;" :: "n"(n) : "memory")

// SMEM: [0..512) colmask; stages @1024 + s*40960; per stage AH+0 AL+10240 BH+20480 BL+30720.
// Row stride 80B (64B data + 16B pad): conflict-free ldmatrix phases.
#define ST_SZ 40960
#define SM_TOTAL (1024 + 2 * ST_SZ)

// ---------------------------------------------------------------------------
// NT GEMM, pre-split fp16 operands: D[128m x 128n] = A . B^T.
// TERMS==3: ah*bh + ah*bl + al*bh. TERMS==2: ah*bh + ah*bl. TERMS==1: ah*bh.
// mode 0: mask+scale -> g_prod; mode 1: split-store -> g_osqTH/L[b][d][t]; mode 2: -> Cout[m][b][n].
// ---------------------------------------------------------------------------
template <int TERMS>
__global__ __launch_bounds__(256, 2) void k_mma(
    int asel, int aBoff, int aShift, int ldA,
    int bsel, int bBoff, int bShift, int ldB,
    int K, int mode, float* __restrict__ Cout,
    const int* __restrict__ maskq, const int* __restrict__ maskn) {
    extern __shared__ char smem[];
    const uint32_t sbase = smem_u32(smem);
    const int tid = threadIdx.x, wid = tid >> 5, l = tid & 31;
    const int b = blockIdx.z;
    const int n0 = blockIdx.x * 128, m0 = blockIdx.y * 128;
    const int NSt = K >> 5;
    constexpr bool useAL = (TERMS == 3);
    constexpr bool useBL = (TERMS >= 2);

    const __half *AH0, *AL0, *BH0, *BL0;
    if (asel == 0)      { AH0 = g_nH;   AL0 = g_nL; }
    else if (asel == 1) { AH0 = g_w2tH; AL0 = g_w2tH; }  // lo unused
    else                { AH0 = g_w1H;  AL0 = g_w1H;  }  // lo unused
    if (bsel == 0)      { BH0 = g_qH;    BL0 = g_qL;    }
    else if (bsel == 1) { BH0 = g_nTH;   BL0 = g_nTL;   }
    else if (bsel == 2) { BH0 = g_qTH;   BL0 = g_qTL;   }
    else                { BH0 = g_osqTH; BL0 = g_osqTL; }
    const size_t aoff = (size_t)(b >> aShift) * aBoff + (size_t)m0 * ldA;
    const size_t boff = (size_t)(b >> bShift) * bBoff + (size_t)n0 * ldB;
    const __half *AH = AH0 + aoff, *AL = AL0 + aoff;
    const __half *BH = BH0 + boff, *BL = BL0 + boff;

    int* colmask = (int*)smem;
    if (mode == 0 && tid < 128) colmask[tid] = maskq[(b >> 5) * 1024 + n0 + tid];

    const int wm = (wid & 1) * 64;
    const int wn = (wid >> 1) * 32;
    const uint32_t a_off = (uint32_t)(l & 15) * 80u + ((uint32_t)(l >> 4) & 1u) * 16u;
    const uint32_t b_off = (uint32_t)((l & 7) + ((l >> 4) << 3)) * 80u + ((uint32_t)(l >> 3) & 1u) * 16u;

    float acc[4][4][4];
#pragma unroll
    for (int i = 0; i < 4; i++)
#pragma unroll
        for (int j = 0; j < 4; j++)
#pragma unroll
            for (int r = 0; r < 4; r++) acc[i][j][r] = 0.f;

    const int cr = tid >> 2, cc = tid & 3;
    {
        uint32_t st = sbase + 1024u;
#pragma unroll
        for (int it = 0; it < 2; it++) {
            int r = cr + it * 64;
            uint32_t d = st + (uint32_t)r * 80u + (uint32_t)cc * 16u;
            CP_ASYNC(d,           AH + (size_t)r * ldA + cc * 8);
            if (useAL) CP_ASYNC(d + 10240u, AL + (size_t)r * ldA + cc * 8);
            CP_ASYNC(d + 20480u,  BH + (size_t)r * ldB + cc * 8);
            if (useBL) CP_ASYNC(d + 30720u, BL + (size_t)r * ldB + cc * 8);
        }
        CP_COMMIT();
    }

    for (int i = 0; i < NSt; i++) {
        if (i + 1 < NSt) {
            const int k0 = (i + 1) * 32;
            uint32_t st = sbase + 1024u + (uint32_t)((i + 1) & 1) * ST_SZ;
#pragma unroll
            for (int it = 0; it < 2; it++) {
                int r = cr + it * 64;
                uint32_t d = st + (uint32_t)r * 80u + (uint32_t)cc * 16u;
                CP_ASYNC(d,           AH + (size_t)r * ldA + k0 + cc * 8);
                if (useAL) CP_ASYNC(d + 10240u, AL + (size_t)r * ldA + k0 + cc * 8);
                CP_ASYNC(d + 20480u,  BH + (size_t)r * ldB + k0 + cc * 8);
                if (useBL) CP_ASYNC(d + 30720u, BL + (size_t)r * ldB + k0 + cc * 8);
            }
            CP_COMMIT();
            CP_WAIT(1);
        } else {
            CP_WAIT(0);
        }
        __syncthreads();

        const uint32_t stg = sbase + 1024u + (uint32_t)(i & 1) * ST_SZ;
#pragma unroll
        for (int s = 0; s < 2; s++) {
            uint32_t bh[4][2], bl[4][2];
#pragma unroll
            for (int p = 0; p < 2; p++) {
                uint32_t rbb = stg + 20480u + (uint32_t)(wn + p * 16) * 80u + b_off + (uint32_t)s * 32u;
                ldsm4(bh[p * 2][0], bh[p * 2][1], bh[p * 2 + 1][0], bh[p * 2 + 1][1], rbb);
                if (useBL)
                    ldsm4(bl[p * 2][0], bl[p * 2][1], bl[p * 2 + 1][0], bl[p * 2 + 1][1], rbb + 10240u);
            }
#pragma unroll
            for (int mf = 0; mf < 4; mf++) {
                uint32_t ah[4], al[4];
                uint32_t raa = stg + (uint32_t)(wm + mf * 16) * 80u + a_off + (uint32_t)s * 32u;
                ldsm4(ah[0], ah[1], ah[2], ah[3], raa);
                if (useAL) ldsm4(al[0], al[1], al[2], al[3], raa + 10240u);
#pragma unroll
                for (int nf = 0; nf < 4; nf++) {
                    mma_f16(acc[mf][nf], ah, bh[nf][0], bh[nf][1]);
                    if (useBL) mma_f16(acc[mf][nf], ah, bl[nf][0], bl[nf][1]);
                    if (useAL) mma_f16(acc[mf][nf], al, bh[nf][0], bh[nf][1]);
                }
            }
        }
        __syncthreads();
    }

    const int rb = l >> 2;
    const int cp = (l & 3) * 2;
    if (mode == 0) {
#pragma unroll
        for (int mf = 0; mf < 4; mf++) {
            const int gr = m0 + wm + mf * 16 + rb;
            const int rm0 = maskn[b * 512 + gr];
            const int rm1 = maskn[b * 512 + gr + 8];
            float* row0 = g_prod + ((size_t)b * 512 + gr) * 1024 + n0 + wn + cp;
#pragma unroll
            for (int nf = 0; nf < 4; nf++) {
                const int q0 = colmask[wn + nf * 8 + cp];
                const int q1 = colmask[wn + nf * 8 + cp + 1];
                float2 v0, v1;
                v0.x = (rm0 | q0) ? MIN_VAL : acc[mf][nf][0] * 0.0625f;
                v0.y = (rm0 | q1) ? MIN_VAL : acc[mf][nf][1] * 0.0625f;
                v1.x = (rm1 | q0) ? MIN_VAL : acc[mf][nf][2] * 0.0625f;
                v1.y = (rm1 | q1) ? MIN_VAL : acc[mf][nf][3] * 0.0625f;
                *(float2*)(row0 + nf * 8) = v0;
                *(float2*)(row0 + 8 * 1024 + nf * 8) = v1;
            }
        }
    } else if (mode == 1) {
        const size_t base = (size_t)b * 262144;
#pragma unroll
        for (int mf = 0; mf < 4; mf++) {
            const int t0 = m0 + wm + mf * 16 + rb;
#pragma unroll
            for (int nf = 0; nf < 4; nf++) {
                const int d0 = n0 + wn + nf * 8 + cp;
#pragma unroll
                for (int r = 0; r < 4; r++) {
                    const size_t idx = base + (size_t)(d0 + (r & 1)) * 1024 + t0 + (r >> 1) * 8;
                    __half h, lo;
                    splitf(acc[mf][nf][r], h, lo);
                    g_osqTH[idx] = h;
                    g_osqTL[idx] = lo;
                }
            }
        }
    } else {
#pragma unroll
        for (int mf = 0; mf < 4; mf++) {
            const int gr = m0 + wm + mf * 16 + rb;
            float* row0 = Cout + (size_t)gr * 32768 + (size_t)b * 256 + n0 + wn + cp;
#pragma unroll
            for (int nf = 0; nf < 4; nf++) {
                float2 v0 = {acc[mf][nf][0], acc[mf][nf][1]};
                float2 v1 = {acc[mf][nf][2], acc[mf][nf][3]};
                *(float2*)(row0 + nf * 8) = v0;
                *(float2*)(row0 + 8 * 32768 + nf * 8) = v1;
            }
        }
    }
}

// ---------------- producers / aux ----------------
__global__ void k_splitnode(const float* __restrict__ node) {
    __shared__ float tile[32][33];
    const int b = blockIdx.z, s0 = blockIdx.x * 32, d0 = blockIdx.y * 32;
    const int tx = threadIdx.x, ty = threadIdx.y;
#pragma unroll
    for (int i = 0; i < 4; i++) {
        int r = ty + i * 8;
        tile[r][tx] = node[(size_t)(s0 + r) * 32768 + (size_t)b * 256 + d0 + tx];
    }
    __syncthreads();
#pragma unroll
    for (int i = 0; i < 4; i++) {
        int r = ty + i * 8;
        __half h, lo;
        splitf(tile[r][tx], h, lo);
        size_t idx = (size_t)b * 131072 + (size_t)(s0 + r) * 256 + d0 + tx;
        g_nH[idx] = h; g_nL[idx] = lo;
        splitf(tile[tx][r], h, lo);
        idx = (size_t)b * 131072 + (size_t)(d0 + r) * 512 + s0 + tx;
        g_nTH[idx] = h; g_nTL[idx] = lo;
    }
}

__global__ void k_splitquery(const float* __restrict__ query) {
    __shared__ float tile[32][33];
    const int b1 = blockIdx.z, t0 = blockIdx.x * 32, d0 = blockIdx.y * 32;
    const int tx = threadIdx.x, ty = threadIdx.y;
#pragma unroll
    for (int i = 0; i < 4; i++) {
        int r = ty + i * 8;
        tile[r][tx] = query[(size_t)(t0 + r) * 1024 + (size_t)b1 * 256 + d0 + tx];
    }
    __syncthreads();
#pragma unroll
    for (int i = 0; i < 4; i++) {
        int r = ty + i * 8;
        __half h, lo;
        splitf(tile[r][tx], h, lo);
        size_t idx = (size_t)b1 * 262144 + (size_t)(t0 + r) * 256 + d0 + tx;
        g_qH[idx] = h; g_qL[idx] = lo;
        splitf(tile[tx][r], h, lo);
        idx = (size_t)b1 * 262144 + (size_t)(d0 + r) * 1024 + t0 + tx;
        g_qTH[idx] = h; g_qTL[idx] = lo;
    }
}

__global__ __launch_bounds__(256) void k_colinv() {
    const int b = blockIdx.y;
    const int t = blockIdx.x * 256 + threadIdx.x;
    const float* P = g_prod + (size_t)b * 524288 + t;
    float L = 0.f;
    for (int s = 0; s < 512; s++) L += expf(P[(size_t)s * 1024]);
    g_colinv[b * 1024 + t] = (L > 0.f) ? 1.f / L : 0.f;
}

__global__ void k_w2t() { // w2tH[b][t][s] = fp16(exp(prod[b,s,t]) * colinv[b,t])
    __shared__ float tile[32][33];
    __shared__ float sinv[32];
    const int b = blockIdx.z, s0 = blockIdx.x * 32, t0 = blockIdx.y * 32;
    const int tx = threadIdx.x, ty = threadIdx.y;
    if (ty == 0) sinv[tx] = g_colinv[b * 1024 + t0 + tx];
#pragma unroll
    for (int i = 0; i < 4; i++) {
        int r = ty + i * 8;
        tile[r][tx] = expf(g_prod[(size_t)b * 524288 + (size_t)(s0 + r) * 1024 + t0 + tx]);
    }
    __syncthreads();
#pragma unroll
    for (int i = 0; i < 4; i++) {
        int r = ty + i * 8;
        g_w2tH[(size_t)b * 524288 + (size_t)(t0 + r) * 512 + s0 + tx] =
            __float2half_rn(tile[tx][r] * sinv[r]);
    }
}

__global__ __launch_bounds__(256) void k_rowsoftmax() { // w1H[b][s][t] from g_prod
    const size_t rowi = blockIdx.x;
    const float* P = g_prod + rowi * 1024;
    const int tid = threadIdx.x;
    float4 v = *((const float4*)P + tid);
    float e0 = expf(v.x), e1 = expf(v.y), e2 = expf(v.z), e3 = expf(v.w);
    float s = e0 + e1 + e2 + e3;
#pragma unroll
    for (int o = 16; o; o >>= 1) s += __shfl_xor_sync(0xffffffffu, s, o);
    __shared__ float ssum[8];
    if ((tid & 31) == 0) ssum[tid >> 5] = s;
    __syncthreads();
    float S = 0.f;
#pragma unroll
    for (int i = 0; i < 8; i++) S += ssum[i];
    const float inv = (S > 0.f) ? 1.f / S : 0.f;
    __half h[4] = {__float2half_rn(e0 * inv), __float2half_rn(e1 * inv),
                   __float2half_rn(e2 * inv), __float2half_rn(e3 * inv)};
    *(uint2*)(g_w1H + rowi * 1024 + tid * 4) = *(uint2*)h;
}

__global__ void k_tosq(float* __restrict__ out_sq) { // out_sq[t,b,d] = hi+lo from osqTH/L[b][d][t]
    __shared__ float tile[32][33];
    const int b = blockIdx.z, t0 = blockIdx.x * 32, d0 = blockIdx.y * 32;
    const int tx = threadIdx.x, ty = threadIdx.y;
#pragma unroll
    for (int i = 0; i < 4; i++) {
        int r = ty + i * 8;
        size_t idx = (size_t)b * 262144 + (size_t)(d0 + r) * 1024 + t0 + tx;
        tile[r][tx] = __half2float(g_osqTH[idx]) + __half2float(g_osqTL[idx]);
    }
    __syncthreads();
#pragma unroll
    for (int i = 0; i < 4; i++) {
        int r = ty + i * 8;
        out_sq[(size_t)(t0 + r) * 32768 + (size_t)b * 256 + d0 + tx] = tile[tx][r];
    }
}

// ---------------------------------------------------------------------------
extern "C" void kernel_launch(void* const* d_in, const int* in_sizes, int n_in,
                              void* d_out, int out_size) {
    const float* query = (const float*)d_in[0];
    const float* node  = (const float*)d_in[1];
    const int*   maskq = (const int*)d_in[2];
    const int*   maskn = (const int*)d_in[3];

    float* out_ss = (float*)d_out;
    float* out_sq = out_ss + (size_t)512 * 128 * 256;
    float* out_cs = out_sq + (size_t)1024 * 128 * 256;

    cudaFuncSetAttribute(k_mma<2>, cudaFuncAttributeMaxDynamicSharedMemorySize, SM_TOTAL);
    cudaFuncSetAttribute(k_mma<1>, cudaFuncAttributeMaxDynamicSharedMemorySize, SM_TOTAL);

    k_splitnode<<<dim3(16, 8, 128), dim3(32, 8)>>>(node);
    k_splitquery<<<dim3(32, 8, 4), dim3(32, 8)>>>(query);
    // G1 (2-term): prod = node . query^T. A=nH ld256, B=qH/qL[b>>5] ld256, K=256.
    k_mma<2><<<dim3(8, 4, 128), 256, SM_TOTAL>>>(0, 131072, 0, 256,
                                                 0, 262144, 5, 256, 256, 0, nullptr, maskq, maskn);
    k_colinv<<<dim3(4, 128), 256>>>();
    k_w2t<<<dim3(16, 32, 128), dim3(32, 8)>>>();
    k_rowsoftmax<<<65536, 256>>>();
    // G2 (2-term): osqT[b][d][t] = w2t . nodeT^T. K=512, M=1024, N=256.
    k_mma<2><<<dim3(2, 8, 128), 256, SM_TOTAL>>>(1, 524288, 0, 512,
                                                 1, 131072, 0, 512, 512, 1, nullptr, maskq, maskn);
    k_tosq<<<dim3(32, 8, 128), dim3(32, 8)>>>(out_sq);
    // G3 (1-term): out_ss = w1 . qT^T. K=1024, M=512, N=256.
    k_mma<1><<<dim3(2, 4, 128), 256, SM_TOTAL>>>(2, 524288, 0, 1024,
                                                 2, 262144, 5, 1024, 1024, 2, out_ss, maskq, maskn);
    // G4 (1-term): cs = w1 . osqT^T.
    k_mma<1><<<dim3(2, 4, 128), 256, SM_TOTAL>>>(2, 524288, 0, 1024,
                                                 3, 262144, 0, 1024, 1024, 2, out_cs, maskq, maskn);
}

// round 15
// speedup vs baseline: 3.7450x; 1.0666x over previous
#include <cuda_runtime.h>
#include <cuda_fp16.h>
#include <math.h>
#include <stdint.h>

// query [1024,4,256] f32, node [512,128,256] f32, maskq [4,1024] i32, maskn [128,512] i32.
// out: out_ss [512,128,256], out_sq [1024,128,256], cs [512,128,256].

// ---------------- scratch (static device) ----------------
static __device__ __half g_expH[67108864];      // [128][512][1024] exp(masked score) fp16
static __device__ float g_colpart[1048576];     // [8][128][1024] col-sum partials (slot = m0tile*2 + warp)
static __device__ __half g_w1H[67108864];       // wts1 [b][s][t]
static __device__ __half g_w2tH[67108864];      // wts2 [b][t][s]
static __device__ __half g_nH[16777216];        // node hi  [b][s][d]
static __device__ __half g_nL[16777216];
static __device__ __half g_nTH[16777216];       // node hi  [b][d][s]
static __device__ __half g_nTL[16777216];
static __device__ __half g_qH[1048576];         // query hi [b1][t][d]
static __device__ __half g_qL[1048576];
static __device__ __half g_qTH[1048576];        // query hi [b1][d][t]
static __device__ __half g_qTL[1048576];
static __device__ __half g_osqTH[33554432];     // out_sq fp16 [b][d][t]

// ---------------- helpers ----------------
__device__ __forceinline__ uint32_t smem_u32(const void* p) {
    uint32_t a;
    asm("{ .reg .u64 t; cvta.to.shared.u64 t, %1; cvt.u32.u64 %0, t; }" : "=r"(a) : "l"(p));
    return a;
}
__device__ __forceinline__ void ldsm4(uint32_t& r0, uint32_t& r1, uint32_t& r2, uint32_t& r3, uint32_t addr) {
    asm volatile("ldmatrix.sync.aligned.m8n8.x4.shared.b16 {%0,%1,%2,%3}, [%4];"
                 : "=r"(r0), "=r"(r1), "=r"(r2), "=r"(r3) : "r"(addr));
}
__device__ __forceinline__ void mma_f16(float* d, const uint32_t* a, uint32_t b0, uint32_t b1) {
    asm volatile("mma.sync.aligned.m16n8k16.row.col.f32.f16.f16.f32 "
                 "{%0,%1,%2,%3}, {%4,%5,%6,%7}, {%8,%9}, {%0,%1,%2,%3};"
                 : "+f"(d[0]), "+f"(d[1]), "+f"(d[2]), "+f"(d[3])
                 : "r"(a[0]), "r"(a[1]), "r"(a[2]), "r"(a[3]), "r"(b0), "r"(b1));
}
__device__ __forceinline__ void splitf(float v, __half& h, __half& lo) {
    h = __float2half_rn(v);
    lo = __float2half_rn(v - __half2float(h));
}
#define CP_ASYNC(dst, src) asm volatile("cp.async.cg.shared.global [%0], [%1], 16;" :: "r"(dst), "l"(src))
#define CP_COMMIT()        asm volatile("cp.async.commit_group;" ::: "memory")
#define CP_WAIT(n)         asm volatile("cp.async.wait_group %0;" :: "n"(n) : "memory")

// SMEM: [0..512) colmask; stages @1024 + s*40960; per stage AH+0 AL+10240 BH+20480 BL+30720.
#define ST_SZ 40960
#define SM_TOTAL (1024 + 2 * ST_SZ)

// ---------------------------------------------------------------------------
// NT GEMM, pre-split fp16 operands: D[128m x 128n] = A . B^T.
// TERMS==2: ah*bh + ah*bl. TERMS==1: ah*bh.
// mode 0: mask+scale+exp -> g_expH (fp16) + per-warp col partial sums -> g_colpart;
// mode 1: fp16 -> g_osqTH[b][d][t]; mode 2: fp32 -> Cout[m][b][n].
// ---------------------------------------------------------------------------
template <int TERMS>
__global__ __launch_bounds__(256, 2) void k_mma(
    int asel, int aBoff, int aShift, int ldA,
    int bsel, int bBoff, int bShift, int ldB,
    int K, int mode, float* __restrict__ Cout,
    const int* __restrict__ maskq, const int* __restrict__ maskn) {
    extern __shared__ char smem[];
    const uint32_t sbase = smem_u32(smem);
    const int tid = threadIdx.x, wid = tid >> 5, l = tid & 31;
    const int b = blockIdx.z;
    const int n0 = blockIdx.x * 128, m0 = blockIdx.y * 128;
    const int NSt = K >> 5;
    constexpr bool useBL = (TERMS >= 2);

    const __half *AH0, *BH0, *BL0;
    if (asel == 0)      AH0 = g_nH;
    else if (asel == 1) AH0 = g_w2tH;
    else                AH0 = g_w1H;
    if (bsel == 0)      { BH0 = g_qH;    BL0 = g_qL;  }
    else if (bsel == 1) { BH0 = g_nTH;   BL0 = g_nTL; }
    else if (bsel == 2) { BH0 = g_qTH;   BL0 = g_qTL; }
    else                { BH0 = g_osqTH; BL0 = g_osqTH; }
    const size_t aoff = (size_t)(b >> aShift) * aBoff + (size_t)m0 * ldA;
    const size_t boff = (size_t)(b >> bShift) * bBoff + (size_t)n0 * ldB;
    const __half *AH = AH0 + aoff;
    const __half *BH = BH0 + boff, *BL = BL0 + boff;

    int* colmask = (int*)smem;
    if (mode == 0 && tid < 128) colmask[tid] = maskq[(b >> 5) * 1024 + n0 + tid];

    const int wm = (wid & 1) * 64;
    const int wn = (wid >> 1) * 32;
    const uint32_t a_off = (uint32_t)(l & 15) * 80u + ((uint32_t)(l >> 4) & 1u) * 16u;
    const uint32_t b_off = (uint32_t)((l & 7) + ((l >> 4) << 3)) * 80u + ((uint32_t)(l >> 3) & 1u) * 16u;

    float acc[4][4][4];
#pragma unroll
    for (int i = 0; i < 4; i++)
#pragma unroll
        for (int j = 0; j < 4; j++)
#pragma unroll
            for (int r = 0; r < 4; r++) acc[i][j][r] = 0.f;

    const int cr = tid >> 2, cc = tid & 3;
    {
        uint32_t st = sbase + 1024u;
#pragma unroll
        for (int it = 0; it < 2; it++) {
            int r = cr + it * 64;
            uint32_t d = st + (uint32_t)r * 80u + (uint32_t)cc * 16u;
            CP_ASYNC(d,           AH + (size_t)r * ldA + cc * 8);
            CP_ASYNC(d + 20480u,  BH + (size_t)r * ldB + cc * 8);
            if (useBL) CP_ASYNC(d + 30720u, BL + (size_t)r * ldB + cc * 8);
        }
        CP_COMMIT();
    }

    for (int i = 0; i < NSt; i++) {
        if (i + 1 < NSt) {
            const int k0 = (i + 1) * 32;
            uint32_t st = sbase + 1024u + (uint32_t)((i + 1) & 1) * ST_SZ;
#pragma unroll
            for (int it = 0; it < 2; it++) {
                int r = cr + it * 64;
                uint32_t d = st + (uint32_t)r * 80u + (uint32_t)cc * 16u;
                CP_ASYNC(d,           AH + (size_t)r * ldA + k0 + cc * 8);
                CP_ASYNC(d + 20480u,  BH + (size_t)r * ldB + k0 + cc * 8);
                if (useBL) CP_ASYNC(d + 30720u, BL + (size_t)r * ldB + k0 + cc * 8);
            }
            CP_COMMIT();
            CP_WAIT(1);
        } else {
            CP_WAIT(0);
        }
        __syncthreads();

        const uint32_t stg = sbase + 1024u + (uint32_t)(i & 1) * ST_SZ;
#pragma unroll
        for (int s = 0; s < 2; s++) {
            uint32_t bh[4][2], bl[4][2];
#pragma unroll
            for (int p = 0; p < 2; p++) {
                uint32_t rbb = stg + 20480u + (uint32_t)(wn + p * 16) * 80u + b_off + (uint32_t)s * 32u;
                ldsm4(bh[p * 2][0], bh[p * 2][1], bh[p * 2 + 1][0], bh[p * 2 + 1][1], rbb);
                if (useBL)
                    ldsm4(bl[p * 2][0], bl[p * 2][1], bl[p * 2 + 1][0], bl[p * 2 + 1][1], rbb + 10240u);
            }
#pragma unroll
            for (int mf = 0; mf < 4; mf++) {
                uint32_t ah[4];
                uint32_t raa = stg + (uint32_t)(wm + mf * 16) * 80u + a_off + (uint32_t)s * 32u;
                ldsm4(ah[0], ah[1], ah[2], ah[3], raa);
#pragma unroll
                for (int nf = 0; nf < 4; nf++) {
                    mma_f16(acc[mf][nf], ah, bh[nf][0], bh[nf][1]);
                    if (useBL) mma_f16(acc[mf][nf], ah, bl[nf][0], bl[nf][1]);
                }
            }
        }
        __syncthreads();
    }

    const int rb = l >> 2;
    const int cp = (l & 3) * 2;
    if (mode == 0) {
        // mask + scale + exp -> fp16 store; per-warp column partial sums -> dedicated slot
        float cs0[4] = {0.f, 0.f, 0.f, 0.f}, cs1[4] = {0.f, 0.f, 0.f, 0.f};
#pragma unroll
        for (int mf = 0; mf < 4; mf++) {
            const int gr = m0 + wm + mf * 16 + rb;
            const int rm0 = maskn[b * 512 + gr];
            const int rm1 = maskn[b * 512 + gr + 8];
            __half* row0 = g_expH + ((size_t)b * 512 + gr) * 1024 + n0 + wn + cp;
#pragma unroll
            for (int nf = 0; nf < 4; nf++) {
                const int q0 = colmask[wn + nf * 8 + cp];
                const int q1 = colmask[wn + nf * 8 + cp + 1];
                float e0 = (rm0 | q0) ? 0.f : expf(acc[mf][nf][0] * 0.0625f);
                float e1 = (rm0 | q1) ? 0.f : expf(acc[mf][nf][1] * 0.0625f);
                float e2 = (rm1 | q0) ? 0.f : expf(acc[mf][nf][2] * 0.0625f);
                float e3 = (rm1 | q1) ? 0.f : expf(acc[mf][nf][3] * 0.0625f);
                *(__half2*)(row0 + nf * 8) = __floats2half2_rn(e0, e1);
                *(__half2*)(row0 + 8 * 1024 + nf * 8) = __floats2half2_rn(e2, e3);
                cs0[nf] += e0 + e2;
                cs1[nf] += e1 + e3;
            }
        }
#pragma unroll
        for (int nf = 0; nf < 4; nf++) {
#pragma unroll
            for (int o = 4; o < 32; o <<= 1) {
                cs0[nf] += __shfl_xor_sync(0xffffffffu, cs0[nf], o);
                cs1[nf] += __shfl_xor_sync(0xffffffffu, cs1[nf], o);
            }
        }
        if (l < 4) {
            const int slot = blockIdx.y * 2 + (wid & 1);
            float* csb = g_colpart + (size_t)slot * 131072 + b * 1024 + n0 + wn + cp;
#pragma unroll
            for (int nf = 0; nf < 4; nf++) {
                csb[nf * 8] = cs0[nf];
                csb[nf * 8 + 1] = cs1[nf];
            }
        }
    } else if (mode == 1) {
        const size_t base = (size_t)b * 262144;
#pragma unroll
        for (int mf = 0; mf < 4; mf++) {
            const int t0 = m0 + wm + mf * 16 + rb;
#pragma unroll
            for (int nf = 0; nf < 4; nf++) {
                const int d0 = n0 + wn + nf * 8 + cp;
#pragma unroll
                for (int r = 0; r < 4; r++) {
                    const size_t idx = base + (size_t)(d0 + (r & 1)) * 1024 + t0 + (r >> 1) * 8;
                    g_osqTH[idx] = __float2half_rn(acc[mf][nf][r]);
                }
            }
        }
    } else {
#pragma unroll
        for (int mf = 0; mf < 4; mf++) {
            const int gr = m0 + wm + mf * 16 + rb;
            float* row0 = Cout + (size_t)gr * 32768 + (size_t)b * 256 + n0 + wn + cp;
#pragma unroll
            for (int nf = 0; nf < 4; nf++) {
                float2 v0 = {acc[mf][nf][0], acc[mf][nf][1]};
                float2 v1 = {acc[mf][nf][2], acc[mf][nf][3]};
                *(float2*)(row0 + nf * 8) = v0;
                *(float2*)(row0 + 8 * 32768 + nf * 8) = v1;
            }
        }
    }
}

// ---------------- producers / aux ----------------
__global__ void k_splitnode(const float* __restrict__ node) {
    __shared__ float tile[32][33];
    const int b = blockIdx.z, s0 = blockIdx.x * 32, d0 = blockIdx.y * 32;
    const int tx = threadIdx.x, ty = threadIdx.y;
#pragma unroll
    for (int i = 0; i < 4; i++) {
        int r = ty + i * 8;
        tile[r][tx] = node[(size_t)(s0 + r) * 32768 + (size_t)b * 256 + d0 + tx];
    }
    __syncthreads();
#pragma unroll
    for (int i = 0; i < 4; i++) {
        int r = ty + i * 8;
        __half h, lo;
        splitf(tile[r][tx], h, lo);
        size_t idx = (size_t)b * 131072 + (size_t)(s0 + r) * 256 + d0 + tx;
        g_nH[idx] = h; g_nL[idx] = lo;
        splitf(tile[tx][r], h, lo);
        idx = (size_t)b * 131072 + (size_t)(d0 + r) * 512 + s0 + tx;
        g_nTH[idx] = h; g_nTL[idx] = lo;
    }
}

__global__ void k_splitquery(const float* __restrict__ query) {
    __shared__ float tile[32][33];
    const int b1 = blockIdx.z, t0 = blockIdx.x * 32, d0 = blockIdx.y * 32;
    const int tx = threadIdx.x, ty = threadIdx.y;
#pragma unroll
    for (int i = 0; i < 4; i++) {
        int r = ty + i * 8;
        tile[r][tx] = query[(size_t)(t0 + r) * 1024 + (size_t)b1 * 256 + d0 + tx];
    }
    __syncthreads();
#pragma unroll
    for (int i = 0; i < 4; i++) {
        int r = ty + i * 8;
        __half h, lo;
        splitf(tile[r][tx], h, lo);
        size_t idx = (size_t)b1 * 262144 + (size_t)(t0 + r) * 256 + d0 + tx;
        g_qH[idx] = h; g_qL[idx] = lo;
        splitf(tile[tx][r], h, lo);
        idx = (size_t)b1 * 262144 + (size_t)(d0 + r) * 1024 + t0 + tx;
        g_qTH[idx] = h; g_qTL[idx] = lo;
    }
}

__global__ void k_w2t() { // w2tH[b][t][s] = expH[b][s][t] / colsum[b][t]
    __shared__ float tile[32][33];
    __shared__ float sinv[32];
    const int b = blockIdx.z, s0 = blockIdx.x * 32, t0 = blockIdx.y * 32;
    const int tx = threadIdx.x, ty = threadIdx.y;
    if (ty == 0) {
        float L = 0.f;
#pragma unroll
        for (int p = 0; p < 8; p++) L += g_colpart[(size_t)p * 131072 + b * 1024 + t0 + tx];
        sinv[tx] = (L > 0.f) ? 1.f / L : 0.f;
    }
#pragma unroll
    for (int i = 0; i < 4; i++) {
        int r = ty + i * 8;
        tile[r][tx] = __half2float(g_expH[(size_t)b * 524288 + (size_t)(s0 + r) * 1024 + t0 + tx]);
    }
    __syncthreads();
#pragma unroll
    for (int i = 0; i < 4; i++) {
        int r = ty + i * 8;
        g_w2tH[(size_t)b * 524288 + (size_t)(t0 + r) * 512 + s0 + tx] =
            __float2half_rn(tile[tx][r] * sinv[r]);
    }
}

__global__ __launch_bounds__(256) void k_rowsoftmax() { // w1H[b][s][t] = expH / rowsum
    const size_t rowi = blockIdx.x;
    const __half* P = g_expH + rowi * 1024;
    const int tid = threadIdx.x;
    uint2 raw = *((const uint2*)P + tid);
    __half2 p01 = *(__half2*)&raw.x, p23 = *(__half2*)&raw.y;
    float e0 = __low2float(p01), e1 = __high2float(p01);
    float e2 = __low2float(p23), e3 = __high2float(p23);
    float s = e0 + e1 + e2 + e3;
#pragma unroll
    for (int o = 16; o; o >>= 1) s += __shfl_xor_sync(0xffffffffu, s, o);
    __shared__ float ssum[8];
    if ((tid & 31) == 0) ssum[tid >> 5] = s;
    __syncthreads();
    float S = 0.f;
#pragma unroll
    for (int i = 0; i < 8; i++) S += ssum[i];
    const float inv = (S > 0.f) ? 1.f / S : 0.f;
    __half2 o01 = __floats2half2_rn(e0 * inv, e1 * inv);
    __half2 o23 = __floats2half2_rn(e2 * inv, e3 * inv);
    uint2 out = {*(uint32_t*)&o01, *(uint32_t*)&o23};
    *((uint2*)(g_w1H + rowi * 1024) + tid) = out;
}

__global__ void k_tosq(float* __restrict__ out_sq) { // out_sq[t,b,d] from osqTH[b][d][t]
    __shared__ float tile[32][33];
    const int b = blockIdx.z, t0 = blockIdx.x * 32, d0 = blockIdx.y * 32;
    const int tx = threadIdx.x, ty = threadIdx.y;
#pragma unroll
    for (int i = 0; i < 4; i++) {
        int r = ty + i * 8;
        tile[r][tx] = __half2float(g_osqTH[(size_t)b * 262144 + (size_t)(d0 + r) * 1024 + t0 + tx]);
    }
    __syncthreads();
#pragma unroll
    for (int i = 0; i < 4; i++) {
        int r = ty + i * 8;
        out_sq[(size_t)(t0 + r) * 32768 + (size_t)b * 256 + d0 + tx] = tile[tx][r];
    }
}

// ---------------------------------------------------------------------------
extern "C" void kernel_launch(void* const* d_in, const int* in_sizes, int n_in,
                              void* d_out, int out_size) {
    const float* query = (const float*)d_in[0];
    const float* node  = (const float*)d_in[1];
    const int*   maskq = (const int*)d_in[2];
    const int*   maskn = (const int*)d_in[3];

    float* out_ss = (float*)d_out;
    float* out_sq = out_ss + (size_t)512 * 128 * 256;
    float* out_cs = out_sq + (size_t)1024 * 128 * 256;

    cudaFuncSetAttribute(k_mma<2>, cudaFuncAttributeMaxDynamicSharedMemorySize, SM_TOTAL);
    cudaFuncSetAttribute(k_mma<1>, cudaFuncAttributeMaxDynamicSharedMemorySize, SM_TOTAL);

    k_splitnode<<<dim3(16, 8, 128), dim3(32, 8)>>>(node);
    k_splitquery<<<dim3(32, 8, 4), dim3(32, 8)>>>(query);
    // G1 (2-term): expH = exp(mask(node . query^T * scale)) + col partial sums. K=256.
    k_mma<2><<<dim3(8, 4, 128), 256, SM_TOTAL>>>(0, 131072, 0, 256,
                                                 0, 262144, 5, 256, 256, 0, nullptr, maskq, maskn);
    k_w2t<<<dim3(16, 32, 128), dim3(32, 8)>>>();
    k_rowsoftmax<<<65536, 256>>>();
    // G2 (2-term): osqTH[b][d][t] = w2t . nodeT^T. K=512, M=1024, N=256.
    k_mma<2><<<dim3(2, 8, 128), 256, SM_TOTAL>>>(1, 524288, 0, 512,
                                                 1, 131072, 0, 512, 512, 1, nullptr, maskq, maskn);
    k_tosq<<<dim3(32, 8, 128), dim3(32, 8)>>>(out_sq);
    // G3 (1-term): out_ss = w1 . qT^T. K=1024, M=512, N=256.
    k_mma<1><<<dim3(2, 4, 128), 256, SM_TOTAL>>>(2, 524288, 0, 1024,
                                                 2, 262144, 5, 1024, 1024, 2, out_ss, maskq, maskn);
    // G4 (1-term): cs = w1 . osqTH^T.
    k_mma<1><<<dim3(2, 4, 128), 256, SM_TOTAL>>>(2, 524288, 0, 1024,
                                                 3, 262144, 0, 1024, 1024, 2, out_cs, maskq, maskn);
}